// round 8
// baseline (speedup 1.0000x reference)
#include <cuda_runtime.h>
#include <cuda_bf16.h>
#include <cstdint>

// ---------------- problem constants ----------------
#define NN   4096
#define HH   128
#define BB   64
#define E0C  131072
#define NEC  135168
#define KKC  52
#define NKC  3328
#define NSLOPE 0.01f

// output layout (floats)
#define OFF_XOUT 0
#define OFF_A2   (NKC*HH)
#define OFF_BATCH (OFF_A2 + (size_t)NKC*NKC)
#define OFF_PERM  (OFF_BATCH + NKC)

// ---------------- scratch layout ----------------
constexpr size_t O_DEG    = 0;
constexpr size_t O_DINV   = (size_t)NN;
constexpr size_t O_CNTC   = (size_t)2*NN;
constexpr size_t O_CNTR   = (size_t)3*NN;
constexpr size_t O_COLPTR = (size_t)4*NN;
constexpr size_t O_ROWPTR = O_COLPTR + NN + 4;
constexpr size_t O_COLCUR = O_ROWPTR + NN + 4;
constexpr size_t O_ROWCUR = O_COLCUR + NN;
constexpr size_t O_COLR   = O_ROWCUR + NN;
constexpr size_t O_COLEW  = O_COLR + NEC;
constexpr size_t O_ECOL   = O_COLEW + NEC;
constexpr size_t O_ROWC   = O_ECOL + NEC;
constexpr size_t O_ROWEW  = O_ROWC + NEC;
constexpr size_t O_ROWEP  = O_ROWEW + NEC;
constexpr size_t O_XQ     = O_ROWEP + NEC;
constexpr size_t O_TMP    = O_XQ  + (size_t)NN*128;
constexpr size_t O_AGG    = O_TMP + (size_t)NN*128;
constexpr size_t O_G0     = O_AGG + (size_t)NN*128;     // 2*NN*128
constexpr size_t O_XC     = O_G0  + (size_t)2*NN*128;
constexpr size_t O_XQ2    = O_XC  + (size_t)NN*128;
constexpr size_t O_F1     = O_XQ2 + (size_t)NN*128;
constexpr size_t O_F2     = O_F1 + NN;
constexpr size_t O_G1S    = O_F2 + NN;
constexpr size_t O_G2S    = O_G1S + NN;
constexpr size_t O_PERM   = O_G2S + NN;
constexpr size_t O_POS    = O_PERM + NKC;
constexpr size_t O_MLOC   = O_POS + NN;                 // NN*KKC
constexpr size_t O_W1E    = O_MLOC + (size_t)NN*KKC;    // 4*384*256
constexpr size_t SCRATCH_ELEMS = O_W1E + (size_t)4*384*256;

__device__ __align__(16) float d_scratch[SCRATCH_ELEMS];

__device__ __forceinline__ float lrelu(float v){ return v >= 0.f ? v : NSLOPE*v; }

// packed fp32x2 fma (Blackwell)
#define FMA2(accv, av, bv) \
    asm("fma.rn.f32x2 %0, %1, %2, %3;" : "=l"(accv) : "l"(av), "l"(bv), "l"(accv))

// ---------------- prep0: zero counters + build folded W1 ----------------
// W1eff[h] (384x256): r<128: W1[r]+W1[256+r]; 128..255: W1[r]-W1[r+128]; 256..383: W1[r+128]
__global__ void prep0(float* zp, const float* __restrict__ W1, float* __restrict__ W1e){
    int b = blockIdx.x;
    if (b < 16){
        for (int i = b*256 + threadIdx.x; i < 4*NN; i += 16*256) zp[i] = 0.f;
        return;
    }
    int idx = (b-16)*256 + threadIdx.x;
    if (idx >= 4*384*256) return;
    int h = idx / (384*256);
    int rem = idx - h*(384*256);
    int r = rem >> 8, c = rem & 255;
    const float* Wh = W1 + (size_t)h*512*256;
    float v;
    if (r < 128)       v = Wh[(size_t)r*256 + c] + Wh[(size_t)(256+r)*256 + c];
    else if (r < 256)  v = Wh[(size_t)r*256 + c] - Wh[(size_t)(r+128)*256 + c];
    else               v = Wh[(size_t)(r+128)*256 + c];
    W1e[idx] = v;
}

// ---------------- graph prep ----------------
__global__ void edge_pass1(const int* __restrict__ ei, const float* __restrict__ w,
                           float* deg, int* cntc, int* cntr){
    int e = blockIdx.x*blockDim.x + threadIdx.x;
    if (e >= NEC) return;
    int r, c; float wv;
    if (e < E0C){ r = ei[e]; c = ei[E0C + e]; wv = w[e]; }
    else        { r = c = e - E0C; wv = 1.f; }
    atomicAdd(&deg[c], wv);
    atomicAdd(&cntc[c], 1);
    atomicAdd(&cntr[r], 1);
}
// grid 3: block 0 = col scan, block 1 = row scan, block 2 = dinv
__global__ void scan_prep(const int* __restrict__ cntc, const int* __restrict__ cntr,
                          int* colPtr, int* colCur, int* rowPtr, int* rowCur,
                          const float* __restrict__ deg, float* __restrict__ dinv){
    if (blockIdx.x == 2){
        for (int i = threadIdx.x; i < NN; i += blockDim.x)
            dinv[i] = rsqrtf(fmaxf(deg[i], 1e-12f));
        return;
    }
    const int* cnt = blockIdx.x ? cntr : cntc;
    int* ptr = blockIdx.x ? rowPtr : colPtr;
    int* cur = blockIdx.x ? rowCur : colCur;
    __shared__ int sh[1024];
    int t = threadIdx.x;
    int v0 = cnt[4*t], v1 = cnt[4*t+1], v2 = cnt[4*t+2], v3 = cnt[4*t+3];
    int s = v0+v1+v2+v3;
    sh[t] = s;
    __syncthreads();
    for (int off = 1; off < 1024; off <<= 1){
        int xv = 0;
        if (t >= off) xv = sh[t-off];
        __syncthreads();
        if (t >= off) sh[t] += xv;
        __syncthreads();
    }
    int incl = sh[t];
    int base = incl - s;
    int p0 = base, p1 = base+v0, p2 = base+v0+v1, p3 = base+v0+v1+v2;
    ptr[4*t] = p0; ptr[4*t+1] = p1; ptr[4*t+2] = p2; ptr[4*t+3] = p3;
    cur[4*t] = p0; cur[4*t+1] = p1; cur[4*t+2] = p2; cur[4*t+3] = p3;
    if (t == 1023) ptr[4096] = incl;
}
__global__ void edge_scatter(const int* __restrict__ ei, const float* __restrict__ w,
                             const float* __restrict__ dinv,
                             int* colCur, int* rowCur,
                             int* colR, float* colEW,
                             int* rowC, float* rowEW, int* rowEp){
    int e = blockIdx.x*blockDim.x + threadIdx.x;
    if (e >= NEC) return;
    int r, c; float wv;
    if (e < E0C){ r = ei[e]; c = ei[E0C + e]; wv = w[e]; }
    else        { r = c = e - E0C; wv = 1.f; }
    float ewv = dinv[r]*wv*dinv[c];
    int p = atomicAdd(&colCur[c], 1);
    colR[p] = r; colEW[p] = ewv;
    int q = atomicAdd(&rowCur[r], 1);
    rowC[q] = c; rowEW[q] = ewv; rowEp[q] = p;
}

// out[c,:] = sum_e wv[e]*vin[colR[e],:]  (warp per node)
__global__ void gather_nodes(const float* __restrict__ vin, float* __restrict__ vout,
                             const int* __restrict__ ptr, const int* __restrict__ rows,
                             const float* __restrict__ wv){
    int node = blockIdx.x*8 + (threadIdx.x >> 5);
    int lane = threadIdx.x & 31;
    if (node >= NN) return;
    int s = ptr[node], e = ptr[node+1];
    float a0=0.f, a1=0.f, a2=0.f, a3=0.f;
    for (int p = s; p < e; p++){
        int r = rows[p]; float w = wv[p];
        const float* vr = vin + (size_t)r*HH;
        a0 = fmaf(w, vr[lane],      a0);
        a1 = fmaf(w, vr[lane+32],   a1);
        a2 = fmaf(w, vr[lane+64],   a2);
        a3 = fmaf(w, vr[lane+96],   a3);
    }
    float* vo = vout + (size_t)node*HH;
    vo[lane]=a0; vo[lane+32]=a1; vo[lane+64]=a2; vo[lane+96]=a3;
}

// ---------------- packed fp32x2 GEMM (64x64 tile, z-batched) — used for linW ----------------
__global__ __launch_bounds__(256) void gemm64p(
        const float* __restrict__ A, const float* __restrict__ B,
        float* __restrict__ C, int M, int N, int K, int leaky,
        size_t Astr, size_t Bstr, size_t Cstr){
    A += blockIdx.z*Astr; B += blockIdx.z*Bstr; C += blockIdx.z*Cstr;
    __shared__ __align__(16) float AsD[16][136];
    __shared__ __align__(16) float Bs[16][68];
    const int tid = threadIdx.x;
    const int tn = tid & 15;
    const int tm = tid >> 4;
    const int row0 = blockIdx.y*64;
    const int col0 = blockIdx.x*64;
    const int arow = tid >> 2;
    const int acol = (tid & 3) << 2;
    const int brow = tid >> 4;
    const int bcol = (tid & 15) << 2;
    unsigned long long acc[4][2];
    #pragma unroll
    for (int i = 0; i < 4; i++){ acc[i][0] = 0ull; acc[i][1] = 0ull; }
    for (int k0 = 0; k0 < K; k0 += 16){
        float4 av = *(const float4*)(A + (size_t)(row0+arow)*K + k0 + acol);
        *(float2*)&AsD[acol+0][2*arow] = make_float2(av.x, av.x);
        *(float2*)&AsD[acol+1][2*arow] = make_float2(av.y, av.y);
        *(float2*)&AsD[acol+2][2*arow] = make_float2(av.z, av.z);
        *(float2*)&AsD[acol+3][2*arow] = make_float2(av.w, av.w);
        float4 bv = *(const float4*)(B + (size_t)(k0+brow)*N + col0 + bcol);
        *(float4*)&Bs[brow][bcol] = bv;
        __syncthreads();
        #pragma unroll
        for (int k = 0; k < 16; k++){
            ulonglong2 aD0 = *reinterpret_cast<const ulonglong2*>(&AsD[k][tm*8]);
            ulonglong2 aD1 = *reinterpret_cast<const ulonglong2*>(&AsD[k][tm*8+4]);
            ulonglong2 bp  = *reinterpret_cast<const ulonglong2*>(&Bs[k][tn*4]);
            FMA2(acc[0][0], aD0.x, bp.x); FMA2(acc[0][1], aD0.x, bp.y);
            FMA2(acc[1][0], aD0.y, bp.x); FMA2(acc[1][1], aD0.y, bp.y);
            FMA2(acc[2][0], aD1.x, bp.x); FMA2(acc[2][1], aD1.x, bp.y);
            FMA2(acc[3][0], aD1.y, bp.x); FMA2(acc[3][1], aD1.y, bp.y);
        }
        __syncthreads();
    }
    #pragma unroll
    for (int i = 0; i < 4; i++){
        int r = row0 + (tm<<2) + i;
        #pragma unroll
        for (int jp = 0; jp < 2; jp++){
            union { unsigned long long u; float2 f; } cv;
            cv.u = acc[i][jp];
            float2 v = cv.f;
            if (leaky){
                v.x = v.x >= 0.f ? v.x : NSLOPE*v.x;
                v.y = v.y >= 0.f ? v.y : NSLOPE*v.y;
            }
            *(float2*)(C + (size_t)r*N + col0 + (tn<<2) + jp*2) = v;
        }
    }
}

// ---------------- fully fused attention ----------------
// grid (64 graphs, 2 heads), 256 threads, dynamic smem.
// Per block: a = kv@Wk; h3=[a,q,a*q] in smem; t1=lrelu(h3@W1e); t2=lrelu(t1@W2);
// logit=lrelu(t2.W3); softmax over 64 nodes -> out[g*64+node].
#define SH_STR  388
#define ST1_STR 260
#define ST2_STR 132
#define SM_SH   0
#define SM_T1   24832            // 64*388
#define SM_ASD  41472            // +64*260
#define SM_BS   43648            // +16*136
#define SM_RED  44736            // +16*68
#define SM_FLOATS 44800          // +64
#define SM_BYTES (SM_FLOATS*4)

__device__ __forceinline__ void fma16t(const float* __restrict__ AsD,
                                       const float* __restrict__ Bs,
                                       int tm, int tn, unsigned long long acc[4][2]){
    #pragma unroll
    for (int k = 0; k < 16; k++){
        ulonglong2 aD0 = *reinterpret_cast<const ulonglong2*>(&AsD[k*136 + tm*8]);
        ulonglong2 aD1 = *reinterpret_cast<const ulonglong2*>(&AsD[k*136 + tm*8 + 4]);
        ulonglong2 bp  = *reinterpret_cast<const ulonglong2*>(&Bs[k*68 + tn*4]);
        FMA2(acc[0][0], aD0.x, bp.x); FMA2(acc[0][1], aD0.x, bp.y);
        FMA2(acc[1][0], aD0.y, bp.x); FMA2(acc[1][1], aD0.y, bp.y);
        FMA2(acc[2][0], aD1.x, bp.x); FMA2(acc[2][1], aD1.x, bp.y);
        FMA2(acc[3][0], aD1.y, bp.x); FMA2(acc[3][1], aD1.y, bp.y);
    }
}
__device__ __forceinline__ void dupA(float* __restrict__ AsD, int arow, int acol, float4 av){
    *(float2*)&AsD[(acol+0)*136 + 2*arow] = make_float2(av.x, av.x);
    *(float2*)&AsD[(acol+1)*136 + 2*arow] = make_float2(av.y, av.y);
    *(float2*)&AsD[(acol+2)*136 + 2*arow] = make_float2(av.z, av.z);
    *(float2*)&AsD[(acol+3)*136 + 2*arow] = make_float2(av.w, av.w);
}

__global__ __launch_bounds__(256) void attn_fused(
    const float* __restrict__ kv, const float* __restrict__ q0,
    const float* __restrict__ tx,
    const float* __restrict__ Wk, const float* __restrict__ W1e,
    const float* __restrict__ W2, const float* __restrict__ W3,
    float* __restrict__ out0, float* __restrict__ out1)
{
    extern __shared__ float sm[];
    float* sH  = sm + SM_SH;
    float* sT1 = sm + SM_T1;
    float* AsD = sm + SM_ASD;
    float* Bs  = sm + SM_BS;
    float* sRed= sm + SM_RED;
    float* sT2 = sm;             // alias (sH dead by phase C writes)

    const int g = blockIdx.x, head = blockIdx.y;
    const int tid = threadIdx.x;
    const int tn = tid & 15, tm = tid >> 4;
    const int arow = tid >> 2, acol = (tid & 3) << 2;
    const int brow = tid >> 4, bcol = (tid & 15) << 2;
    const float* Wkh = Wk  + (size_t)head*128*128;
    const float* W1h = W1e + (size_t)head*384*256;
    const float* W2h = W2  + (size_t)head*256*128;
    const float* W3h = W3  + (size_t)head*128;

    // phase 0: load q into sH[:,128:256)
    for (int idx = tid; idx < 64*128; idx += 256){
        int row = idx >> 7, c = idx & 127;
        float qv = head ? tx[g*128 + c] : q0[(size_t)(g*64+row)*128 + c];
        sH[row*SH_STR + 128 + c] = qv;
    }

    unsigned long long acc[4][2];
    // ---- phase A: a = kv @ Wk ----
    #pragma unroll 1
    for (int ct = 0; ct < 2; ct++){
        #pragma unroll
        for (int i = 0; i < 4; i++){ acc[i][0]=0ull; acc[i][1]=0ull; }
        #pragma unroll 1
        for (int k0 = 0; k0 < 128; k0 += 16){
            __syncthreads();
            float4 av = *(const float4*)(kv + (size_t)(g*64+arow)*128 + k0 + acol);
            dupA(AsD, arow, acol, av);
            float4 bv = *(const float4*)(Wkh + (size_t)(k0+brow)*128 + ct*64 + bcol);
            *(float4*)&Bs[brow*68 + bcol] = bv;
            __syncthreads();
            fma16t(AsD, Bs, tm, tn, acc);
        }
        #pragma unroll
        for (int i = 0; i < 4; i++){
            int row = (tm<<2) + i;
            float* hr = &sH[row*SH_STR];
            #pragma unroll
            for (int jp = 0; jp < 2; jp++){
                union { unsigned long long u; float2 f; } cv; cv.u = acc[i][jp];
                int col = ct*64 + (tn<<2) + jp*2;
                hr[col]   = cv.f.x;
                hr[col+1] = cv.f.y;
                hr[256+col]   = cv.f.x * hr[128+col];
                hr[256+col+1] = cv.f.y * hr[128+col+1];
            }
        }
    }
    // ---- phase B: t1 = lrelu(h3 @ W1e), K=384, N=256 ----
    #pragma unroll 1
    for (int ct = 0; ct < 4; ct++){
        #pragma unroll
        for (int i = 0; i < 4; i++){ acc[i][0]=0ull; acc[i][1]=0ull; }
        #pragma unroll 1
        for (int k0 = 0; k0 < 384; k0 += 16){
            __syncthreads();
            float4 av = *(const float4*)&sH[arow*SH_STR + k0 + acol];
            dupA(AsD, arow, acol, av);
            float4 bv = *(const float4*)(W1h + (size_t)(k0+brow)*256 + ct*64 + bcol);
            *(float4*)&Bs[brow*68 + bcol] = bv;
            __syncthreads();
            fma16t(AsD, Bs, tm, tn, acc);
        }
        #pragma unroll
        for (int i = 0; i < 4; i++){
            int row = (tm<<2) + i;
            #pragma unroll
            for (int jp = 0; jp < 2; jp++){
                union { unsigned long long u; float2 f; } cv; cv.u = acc[i][jp];
                int col = ct*64 + (tn<<2) + jp*2;
                sT1[row*ST1_STR + col]   = lrelu(cv.f.x);
                sT1[row*ST1_STR + col+1] = lrelu(cv.f.y);
            }
        }
    }
    // ---- phase C: t2 = lrelu(t1 @ W2), K=256, N=128 ----
    #pragma unroll 1
    for (int ct = 0; ct < 2; ct++){
        #pragma unroll
        for (int i = 0; i < 4; i++){ acc[i][0]=0ull; acc[i][1]=0ull; }
        #pragma unroll 1
        for (int k0 = 0; k0 < 256; k0 += 16){
            __syncthreads();
            float4 av = *(const float4*)&sT1[arow*ST1_STR + k0 + acol];
            dupA(AsD, arow, acol, av);
            float4 bv = *(const float4*)(W2h + (size_t)(k0+brow)*128 + ct*64 + bcol);
            *(float4*)&Bs[brow*68 + bcol] = bv;
            __syncthreads();
            fma16t(AsD, Bs, tm, tn, acc);
        }
        __syncthreads();   // ct=0 writes alias sH; ensure all fma reads of AsD done (and phase-A region dead)
        #pragma unroll
        for (int i = 0; i < 4; i++){
            int row = (tm<<2) + i;
            #pragma unroll
            for (int jp = 0; jp < 2; jp++){
                union { unsigned long long u; float2 f; } cv; cv.u = acc[i][jp];
                int col = ct*64 + (tn<<2) + jp*2;
                sT2[row*ST2_STR + col]   = lrelu(cv.f.x);
                sT2[row*ST2_STR + col+1] = lrelu(cv.f.y);
            }
        }
    }
    __syncthreads();
    // ---- phase D: logit + segment softmax ----
    {
        int wid = tid >> 5, lane = tid & 31;
        float w0 = W3h[lane], w1 = W3h[lane+32], w2v = W3h[lane+64], w3v = W3h[lane+96];
        #pragma unroll
        for (int rr = 0; rr < 8; rr++){
            int row = wid*8 + rr;
            const float* ar = &sT2[row*ST2_STR];
            float s = ar[lane]*w0 + ar[lane+32]*w1 + ar[lane+64]*w2v + ar[lane+96]*w3v;
            #pragma unroll
            for (int o = 16; o; o >>= 1) s += __shfl_xor_sync(0xffffffffu, s, o);
            if (lane == 0) sRed[row] = lrelu(s);
        }
        __syncthreads();
        float v = 0.f, e = 0.f;
        if (tid < 64){
            v = sRed[tid];
            float m = -1e30f;
            #pragma unroll 8
            for (int j = 0; j < 64; j++) m = fmaxf(m, sRed[j]);
            e = expf(v - m);
        }
        __syncthreads();
        if (tid < 64) Bs[tid] = e;
        __syncthreads();
        if (tid < 64){
            float s = 0.f;
            #pragma unroll 8
            for (int j = 0; j < 64; j++) s += Bs[j];
            float* out = head ? out1 : out0;
            out[g*64 + tid] = e / s;
        }
    }
}

// ---------------- fused edge softmax + aggregation ----------------
__global__ void esm_gather(const int* __restrict__ colPtr, const int* __restrict__ colR,
                           const float* __restrict__ f1, const float* __restrict__ f2,
                           float* __restrict__ Ecol, const float* __restrict__ x,
                           float* __restrict__ agg){
    int node = blockIdx.x*8 + (threadIdx.x >> 5);
    int lane = threadIdx.x & 31;
    if (node >= NN) return;
    int s = colPtr[node], e = colPtr[node+1];
    float f1c = f1[node];
    float mx = -1e30f;
    for (int p = s + lane; p < e; p += 32)
        mx = fmaxf(mx, lrelu(f1c + f2[colR[p]]));
    #pragma unroll
    for (int o = 16; o; o >>= 1) mx = fmaxf(mx, __shfl_xor_sync(0xffffffffu, mx, o));
    float sum = 0.f;
    for (int p = s + lane; p < e; p += 32){
        float ev = expf(lrelu(f1c + f2[colR[p]]) - mx);
        Ecol[p] = ev; sum += ev;
    }
    #pragma unroll
    for (int o = 16; o; o >>= 1) sum += __shfl_xor_sync(0xffffffffu, sum, o);
    float inv = 1.f / sum;
    float a0=0.f, a1=0.f, a2=0.f, a3=0.f;
    for (int p = s; p < e; p++){
        float w = Ecol[p] * inv;
        int r = colR[p];
        const float* vr = x + (size_t)r*HH;
        a0 = fmaf(w, vr[lane],    a0);
        a1 = fmaf(w, vr[lane+32], a1);
        a2 = fmaf(w, vr[lane+64], a2);
        a3 = fmaf(w, vr[lane+96], a3);
        if (lane == 0) Ecol[p] = w;
    }
    float* vo = agg + (size_t)node*HH;
    vo[lane]=a0; vo[lane+32]=a1; vo[lane+64]=a2; vo[lane+96]=a3;
}
__global__ void xc_combine(const float* __restrict__ x, const float* __restrict__ g0,
                           const float* __restrict__ g1, float* __restrict__ xc){
    int idx = blockIdx.x*blockDim.x + threadIdx.x;
    if (idx >= NN*HH) return;
    float xv = x[idx];
    xc[idx] = 0.5f * (lrelu(xv + g0[idx]) + lrelu(xv + g1[idx]));
}

// ---------------- finalize: score softmax + stable top-k + pooled outputs ----------------
__global__ void finalize(const float* __restrict__ g1s, const float* __restrict__ g2s,
                         const float* __restrict__ x,
                         int* __restrict__ perm, int* __restrict__ pos,
                         float* __restrict__ out){
    __shared__ float sv[64], se[64], ssc[64];
    __shared__ int sperm[KKC];
    int b = blockIdx.x, tid = threadIdx.x;
    float v = 0.f, e = 0.f;
    if (tid < 64){
        int i = b*64 + tid;
        v = g1s[i] + g2s[i];
        sv[tid] = v;
    }
    __syncthreads();
    if (tid < 64){
        float m = -1e30f;
        #pragma unroll 8
        for (int j = 0; j < 64; j++) m = fmaxf(m, sv[j]);
        e = expf(v - m);
        se[tid] = e;
    }
    __syncthreads();
    if (tid < 64){
        float s = 0.f;
        #pragma unroll 8
        for (int j = 0; j < 64; j++) s += se[j];
        float sc = e / s;
        ssc[tid] = sc;
        int rank = 0;
        for (int j = 0; j < 64; j++){
            float vj = sv[j];
            if (vj > v || (vj == v && j < tid)) rank++;
        }
        int i = b*64 + tid;
        pos[i] = (rank < KKC) ? b*KKC + rank : -1;
        if (rank < KKC){
            int p = b*KKC + rank;
            sperm[rank] = tid;
            perm[p] = i;
            out[OFF_BATCH + p] = (float)b;
            out[OFF_PERM  + p] = (float)i;
        }
    }
    __syncthreads();
    for (int idx = tid; idx < KKC*128; idx += blockDim.x){
        int p = idx >> 7, c = idx & 127;
        int node = sperm[p];
        out[OFF_XOUT + ((size_t)b*KKC + p)*128 + c] =
            x[(size_t)(b*64 + node)*128 + c] * ssc[node];
    }
}

// ---------------- block-diagonal triple product ----------------
__global__ void spgemm_M(const int* __restrict__ rowPtr, const int* __restrict__ rowC,
                         const float* __restrict__ rowEW, const int* __restrict__ rowEp,
                         const float* __restrict__ Ecol, const int* __restrict__ pos,
                         float* __restrict__ Mloc){
    __shared__ float acc[KKC];
    int i = blockIdx.x;
    int tid = threadIdx.x;
    for (int t = tid; t < KKC; t += blockDim.x) acc[t] = 0.f;
    __syncthreads();
    int b52 = (i >> 6) * KKC;
    int s = rowPtr[i], e = rowPtr[i+1];
    int warp = tid >> 5, lane = tid & 31;
    for (int p = s + warp; p < e; p += 4){
        int j = rowC[p]; float ewv = rowEW[p];
        int s2 = rowPtr[j], e2 = rowPtr[j+1];
        for (int q = s2 + lane; q < e2; q += 32){
            int k = pos[rowC[q]];
            if (k >= 0){
                unsigned kk = (unsigned)(k - b52);
                if (kk < KKC) atomicAdd(&acc[kk], ewv * Ecol[rowEp[q]]);
            }
        }
    }
    __syncthreads();
    for (int t = tid; t < KKC; t += blockDim.x) Mloc[(size_t)i*KKC + t] = acc[t];
}
__global__ void a2_full(const int* __restrict__ colPtr, const int* __restrict__ colR,
                        const float* __restrict__ Ecol, const int* __restrict__ perm,
                        const float* __restrict__ Mloc, float* __restrict__ outA2){
    __shared__ float acc[KKC];
    int p = blockIdx.x;
    int tid = threadIdx.x;
    int g = perm[p];
    int base = (g >> 6) * KKC;
    if (tid < KKC){
        float a = 0.f;
        int s = colPtr[g], e = colPtr[g+1];
        for (int q = s; q < e; q++)
            a = fmaf(Ecol[q], Mloc[(size_t)colR[q]*KKC + tid], a);
        acc[tid] = a;
    }
    __syncthreads();
    float* row = outA2 + (size_t)p*NKC;
    for (int t = tid; t < NKC; t += 256){
        unsigned kk = (unsigned)(t - base);
        float v = (kk < KKC) ? acc[kk] : 0.f;
        if (t == p) v = 1.0f;
        row[t] = v;
    }
}

// ---------------- host launcher ----------------
extern "C" void kernel_launch(void* const* d_in, const int* in_sizes, int n_in,
                              void* d_out, int out_size){
    const float* x    = (const float*)d_in[0];
    const int*   ei   = (const int*)  d_in[1];
    const float* ewt  = (const float*)d_in[2];
    const float* tx   = (const float*)d_in[3];
    const float* Wk   = (const float*)d_in[5];
    const float* W1   = (const float*)d_in[6];
    const float* W2   = (const float*)d_in[7];
    const float* W3   = (const float*)d_in[8];
    const float* linW = (const float*)d_in[9];
    float* out = (float*)d_out;

    void* basep = nullptr;
    cudaGetSymbolAddress(&basep, d_scratch);
    float* base = (float*)basep;

    float* deg    = base + O_DEG;
    float* dinv   = base + O_DINV;
    int*   cntc   = (int*)(base + O_CNTC);
    int*   cntr   = (int*)(base + O_CNTR);
    int*   colPtr = (int*)(base + O_COLPTR);
    int*   rowPtr = (int*)(base + O_ROWPTR);
    int*   colCur = (int*)(base + O_COLCUR);
    int*   rowCur = (int*)(base + O_ROWCUR);
    int*   colR   = (int*)(base + O_COLR);
    float* colEW  = base + O_COLEW;
    float* Ecol   = base + O_ECOL;
    int*   rowC   = (int*)(base + O_ROWC);
    float* rowEW  = base + O_ROWEW;
    int*   rowEp  = (int*)(base + O_ROWEP);
    float* xq     = base + O_XQ;
    float* tmp    = base + O_TMP;
    float* agg    = base + O_AGG;
    float* g0     = base + O_G0;
    float* g1b    = g0 + (size_t)NN*128;
    float* xc     = base + O_XC;
    float* xq2    = base + O_XQ2;
    float* f1     = base + O_F1;
    float* f2     = base + O_F2;
    float* g1s    = base + O_G1S;
    float* g2s    = base + O_G2S;
    int*   perm   = (int*)(base + O_PERM);
    int*   pos    = (int*)(base + O_POS);
    float* Mloc   = base + O_MLOC;
    float* W1e    = base + O_W1E;

    cudaFuncSetAttribute(attn_fused, cudaFuncAttributeMaxDynamicSharedMemorySize, SM_BYTES);

    const int EG = (NEC + 255)/256;
    const size_t S128 = (size_t)NN*128;

    // ---- graph prep (zero + W1 fold fused) ----
    prep0<<<16 + (4*384*256+255)/256, 256>>>(deg, W1, W1e);
    edge_pass1<<<EG,256>>>(ei, ewt, deg, cntc, cntr);
    scan_prep<<<3,1024>>>(cntc, cntr, colPtr, colCur, rowPtr, rowCur, deg, dinv);
    edge_scatter<<<EG,256>>>(ei, ewt, dinv, colCur, rowCur, colR, colEW, rowC, rowEW, rowEp);

    // ---- x_q = hop(hop(x)) ----
    gather_nodes<<<512,256>>>(x,   tmp, colPtr, colR, colEW);
    gather_nodes<<<512,256>>>(tmp, xq,  colPtr, colR, colEW);

    // ---- attention pair 1 (heads 0,1) ----
    attn_fused<<<dim3(BB,2),256,SM_BYTES>>>(x, xq, tx, Wk, W1e, W2, W3, f1, f2);

    // ---- edge softmax + aggregation (fused) ----
    esm_gather<<<512,256>>>(colPtr, colR, f1, f2, Ecol, x, agg);
    gemm64p<<<dim3(2,64,2),256>>>(agg, linW, g0, NN, 128, 128, 0,
                                  0, (size_t)128*128, S128);
    xc_combine<<<2048,256>>>(x, g0, g1b, xc);

    // ---- second round ----
    gather_nodes<<<512,256>>>(xc,  tmp, colPtr, colR, colEW);
    gather_nodes<<<512,256>>>(tmp, xq2, colPtr, colR, colEW);
    attn_fused<<<dim3(BB,2),256,SM_BYTES>>>(xc, xq2, tx,
                                            Wk + (size_t)2*128*128, W1e + (size_t)2*384*256,
                                            W2 + (size_t)2*256*128, W3 + 2*128, g1s, g2s);

    // ---- score softmax + top-k + pooled outputs ----
    finalize<<<BB,256>>>(g1s, g2s, x, perm, pos, out);

    // ---- A2 = S_p^T (A_d S_p), block-diagonal ----
    spgemm_M<<<NN,128>>>(rowPtr, rowC, rowEW, rowEp, Ecol, pos, Mloc);
    a2_full<<<NKC,256>>>(colPtr, colR, Ecol, perm, Mloc, out + OFF_A2);
}

// round 11
// speedup vs baseline: 1.0585x; 1.0585x over previous
#include <cuda_runtime.h>
#include <cuda_bf16.h>
#include <cstdint>

// ---------------- problem constants ----------------
#define NN   4096
#define HH   128
#define BB   64
#define E0C  131072
#define NEC  135168
#define KKC  52
#define NKC  3328
#define NSLOPE 0.01f

// output layout (floats)
#define OFF_XOUT 0
#define OFF_A2   (NKC*HH)
#define OFF_BATCH (OFF_A2 + (size_t)NKC*NKC)
#define OFF_PERM  (OFF_BATCH + NKC)

// ---------------- scratch layout ----------------
constexpr size_t O_DEG    = 0;
constexpr size_t O_DINV   = (size_t)NN;
constexpr size_t O_CNTC   = (size_t)2*NN;
constexpr size_t O_CNTR   = (size_t)3*NN;
constexpr size_t O_COLPTR = (size_t)4*NN;
constexpr size_t O_ROWPTR = O_COLPTR + NN + 4;
constexpr size_t O_COLCUR = O_ROWPTR + NN + 4;
constexpr size_t O_ROWCUR = O_COLCUR + NN;
constexpr size_t O_COLR   = O_ROWCUR + NN;
constexpr size_t O_COLEW  = O_COLR + NEC;
constexpr size_t O_ECOL   = O_COLEW + NEC;
constexpr size_t O_ROWC   = O_ECOL + NEC;
constexpr size_t O_ROWEW  = O_ROWC + NEC;
constexpr size_t O_ROWEP  = O_ROWEW + NEC;
constexpr size_t O_ABUF   = O_ROWEP + NEC;                 // 2*NN*128
constexpr size_t O_H3     = O_ABUF + (size_t)2*NN*128;     // 2*NN*384
constexpr size_t O_T1     = O_H3   + (size_t)2*NN*384;     // 2*NN*256
constexpr size_t O_T2     = O_T1   + (size_t)2*NN*256;     // 2*NN*128
constexpr size_t O_XQ     = O_T2   + (size_t)2*NN*128;
constexpr size_t O_TMP    = O_XQ   + (size_t)NN*128;
constexpr size_t O_AGG    = O_TMP  + (size_t)NN*128;
constexpr size_t O_G0     = O_AGG  + (size_t)NN*128;       // 2*NN*128
constexpr size_t O_XC     = O_G0   + (size_t)2*NN*128;
constexpr size_t O_XQ2    = O_XC   + (size_t)NN*128;
constexpr size_t O_F1     = O_XQ2  + (size_t)NN*128;
constexpr size_t O_F2     = O_F1 + NN;
constexpr size_t O_G1S    = O_F2 + NN;
constexpr size_t O_G2S    = O_G1S + NN;
constexpr size_t O_PERM   = O_G2S + NN;
constexpr size_t O_POS    = O_PERM + NKC;
constexpr size_t O_MLOC   = O_POS + NN;                    // NN*KKC
constexpr size_t O_W1E    = O_MLOC + (size_t)NN*KKC;       // 4*384*256
constexpr size_t SCRATCH_ELEMS = O_W1E + (size_t)4*384*256;

__device__ __align__(16) float d_scratch[SCRATCH_ELEMS];

__device__ __forceinline__ float lrelu(float v){ return v >= 0.f ? v : NSLOPE*v; }

// packed fp32x2 fma (Blackwell)
#define FMA2(accv, av, bv) \
    asm("fma.rn.f32x2 %0, %1, %2, %3;" : "=l"(accv) : "l"(av), "l"(bv), "l"(accv))

// ---------------- prep0: zero counters + build folded W1 ----------------
// W1eff[h] (384x256): r<128: W1[r]+W1[256+r]; 128..255: W1[r]-W1[r+128]; 256..383: W1[r+128]
__global__ void prep0(float* zp, const float* __restrict__ W1, float* __restrict__ W1e){
    int b = blockIdx.x;
    if (b < 16){
        for (int i = b*256 + threadIdx.x; i < 4*NN; i += 16*256) zp[i] = 0.f;
        return;
    }
    int idx = (b-16)*256 + threadIdx.x;
    if (idx >= 4*384*256) return;
    int h = idx / (384*256);
    int rem = idx - h*(384*256);
    int r = rem >> 8, c = rem & 255;
    const float* Wh = W1 + (size_t)h*512*256;
    float v;
    if (r < 128)       v = Wh[(size_t)r*256 + c] + Wh[(size_t)(256+r)*256 + c];
    else if (r < 256)  v = Wh[(size_t)r*256 + c] - Wh[(size_t)(r+128)*256 + c];
    else               v = Wh[(size_t)(r+128)*256 + c];
    W1e[idx] = v;
}

// ---------------- graph prep ----------------
__global__ void edge_pass1(const int* __restrict__ ei, const float* __restrict__ w,
                           float* deg, int* cntc, int* cntr){
    int e = blockIdx.x*blockDim.x + threadIdx.x;
    if (e >= NEC) return;
    int r, c; float wv;
    if (e < E0C){ r = ei[e]; c = ei[E0C + e]; wv = w[e]; }
    else        { r = c = e - E0C; wv = 1.f; }
    atomicAdd(&deg[c], wv);
    atomicAdd(&cntc[c], 1);
    atomicAdd(&cntr[r], 1);
}
// grid 3: block 0 = col scan, block 1 = row scan, block 2 = dinv
__global__ void scan_prep(const int* __restrict__ cntc, const int* __restrict__ cntr,
                          int* colPtr, int* colCur, int* rowPtr, int* rowCur,
                          const float* __restrict__ deg, float* __restrict__ dinv){
    if (blockIdx.x == 2){
        for (int i = threadIdx.x; i < NN; i += blockDim.x)
            dinv[i] = rsqrtf(fmaxf(deg[i], 1e-12f));
        return;
    }
    const int* cnt = blockIdx.x ? cntr : cntc;
    int* ptr = blockIdx.x ? rowPtr : colPtr;
    int* cur = blockIdx.x ? rowCur : colCur;
    __shared__ int sh[1024];
    int t = threadIdx.x;
    int v0 = cnt[4*t], v1 = cnt[4*t+1], v2 = cnt[4*t+2], v3 = cnt[4*t+3];
    int s = v0+v1+v2+v3;
    sh[t] = s;
    __syncthreads();
    for (int off = 1; off < 1024; off <<= 1){
        int xv = 0;
        if (t >= off) xv = sh[t-off];
        __syncthreads();
        if (t >= off) sh[t] += xv;
        __syncthreads();
    }
    int incl = sh[t];
    int base = incl - s;
    int p0 = base, p1 = base+v0, p2 = base+v0+v1, p3 = base+v0+v1+v2;
    ptr[4*t] = p0; ptr[4*t+1] = p1; ptr[4*t+2] = p2; ptr[4*t+3] = p3;
    cur[4*t] = p0; cur[4*t+1] = p1; cur[4*t+2] = p2; cur[4*t+3] = p3;
    if (t == 1023) ptr[4096] = incl;
}
__global__ void edge_scatter(const int* __restrict__ ei, const float* __restrict__ w,
                             const float* __restrict__ dinv,
                             int* colCur, int* rowCur,
                             int* colR, float* colEW,
                             int* rowC, float* rowEW, int* rowEp){
    int e = blockIdx.x*blockDim.x + threadIdx.x;
    if (e >= NEC) return;
    int r, c; float wv;
    if (e < E0C){ r = ei[e]; c = ei[E0C + e]; wv = w[e]; }
    else        { r = c = e - E0C; wv = 1.f; }
    float ewv = dinv[r]*wv*dinv[c];
    int p = atomicAdd(&colCur[c], 1);
    colR[p] = r; colEW[p] = ewv;
    int q = atomicAdd(&rowCur[r], 1);
    rowC[q] = c; rowEW[q] = ewv; rowEp[q] = p;
}

// out[c,:] = sum_e wv[e]*vin[colR[e],:]  (warp per node)
__global__ void gather_nodes(const float* __restrict__ vin, float* __restrict__ vout,
                             const int* __restrict__ ptr, const int* __restrict__ rows,
                             const float* __restrict__ wv){
    int node = blockIdx.x*8 + (threadIdx.x >> 5);
    int lane = threadIdx.x & 31;
    if (node >= NN) return;
    int s = ptr[node], e = ptr[node+1];
    float a0=0.f, a1=0.f, a2=0.f, a3=0.f;
    for (int p = s; p < e; p++){
        int r = rows[p]; float w = wv[p];
        const float* vr = vin + (size_t)r*HH;
        a0 = fmaf(w, vr[lane],      a0);
        a1 = fmaf(w, vr[lane+32],   a1);
        a2 = fmaf(w, vr[lane+64],   a2);
        a3 = fmaf(w, vr[lane+96],   a3);
    }
    float* vo = vout + (size_t)node*HH;
    vo[lane]=a0; vo[lane+32]=a1; vo[lane+64]=a2; vo[lane+96]=a3;
}

// ---------------- packed fp32x2 GEMM (64x128 tile, 4x8 micro, z-batched) ----------------
// C[.,N] tile: rows blockIdx.y*64, cols blockIdx.x*128. K%16==0.
__global__ __launch_bounds__(256) void gemm_t(
        const float* __restrict__ A, const float* __restrict__ B,
        float* __restrict__ C, int N, int K, int leaky,
        size_t Astr, size_t Bstr, size_t Cstr){
    A += blockIdx.z*Astr; B += blockIdx.z*Bstr; C += blockIdx.z*Cstr;
    __shared__ __align__(16) float AsD[16*136];   // duplicated A rows: [k][2m],[2m+1]
    __shared__ __align__(16) float Bs[16*132];
    const int tid = threadIdx.x;
    const int tn = tid & 15;         // 16 col groups x 8 cols
    const int tm = tid >> 4;         // 16 row groups x 4 rows
    const int row0 = blockIdx.y*64;
    const int col0 = blockIdx.x*128;
    const int arow = tid >> 2;
    const int acol = (tid & 3) << 2;
    const int brow = tid >> 4;
    const int bcol = (tid & 15) << 3;
    unsigned long long acc[4][4];
    #pragma unroll
    for (int i = 0; i < 4; i++)
        #pragma unroll
        for (int j = 0; j < 4; j++) acc[i][j] = 0ull;
    for (int k0 = 0; k0 < K; k0 += 16){
        float4 av = *(const float4*)(A + (size_t)(row0+arow)*K + k0 + acol);
        float4 b0 = *(const float4*)(B + (size_t)(k0+brow)*N + col0 + bcol);
        float4 b1 = *(const float4*)(B + (size_t)(k0+brow)*N + col0 + bcol + 4);
        *(float2*)&AsD[(acol+0)*136 + 2*arow] = make_float2(av.x, av.x);
        *(float2*)&AsD[(acol+1)*136 + 2*arow] = make_float2(av.y, av.y);
        *(float2*)&AsD[(acol+2)*136 + 2*arow] = make_float2(av.z, av.z);
        *(float2*)&AsD[(acol+3)*136 + 2*arow] = make_float2(av.w, av.w);
        *(float4*)&Bs[brow*132 + bcol]     = b0;
        *(float4*)&Bs[brow*132 + bcol + 4] = b1;
        __syncthreads();
        #pragma unroll
        for (int k = 0; k < 16; k++){
            ulonglong2 aD0 = *reinterpret_cast<const ulonglong2*>(&AsD[k*136 + tm*8]);
            ulonglong2 aD1 = *reinterpret_cast<const ulonglong2*>(&AsD[k*136 + tm*8 + 4]);
            ulonglong2 bp0 = *reinterpret_cast<const ulonglong2*>(&Bs[k*132 + tn*8]);
            ulonglong2 bp1 = *reinterpret_cast<const ulonglong2*>(&Bs[k*132 + tn*8 + 4]);
            FMA2(acc[0][0], aD0.x, bp0.x); FMA2(acc[0][1], aD0.x, bp0.y);
            FMA2(acc[0][2], aD0.x, bp1.x); FMA2(acc[0][3], aD0.x, bp1.y);
            FMA2(acc[1][0], aD0.y, bp0.x); FMA2(acc[1][1], aD0.y, bp0.y);
            FMA2(acc[1][2], aD0.y, bp1.x); FMA2(acc[1][3], aD0.y, bp1.y);
            FMA2(acc[2][0], aD1.x, bp0.x); FMA2(acc[2][1], aD1.x, bp0.y);
            FMA2(acc[2][2], aD1.x, bp1.x); FMA2(acc[2][3], aD1.x, bp1.y);
            FMA2(acc[3][0], aD1.y, bp0.x); FMA2(acc[3][1], aD1.y, bp0.y);
            FMA2(acc[3][2], aD1.y, bp1.x); FMA2(acc[3][3], aD1.y, bp1.y);
        }
        __syncthreads();
    }
    #pragma unroll
    for (int i = 0; i < 4; i++){
        int r = row0 + (tm<<2) + i;
        float* cr = C + (size_t)r*N + col0 + (tn<<3);
        #pragma unroll
        for (int jp = 0; jp < 4; jp++){
            union { unsigned long long u; float2 f; } cv;
            cv.u = acc[i][jp];
            float2 v = cv.f;
            if (leaky){
                v.x = v.x >= 0.f ? v.x : NSLOPE*v.x;
                v.y = v.y >= 0.f ? v.y : NSLOPE*v.y;
            }
            *(float2*)(cr + jp*2) = v;
        }
    }
}

// ---------------- attention helpers ----------------
// h3 = [a, q, a*q]  (per head via blockIdx.y; head 1 reads target_x directly)
__global__ void build_h3(const float* __restrict__ aab, const float* __restrict__ q0,
                         const float* __restrict__ tx, float* __restrict__ h3){
    int idx = blockIdx.x*blockDim.x + threadIdx.x;
    if (idx >= NN*HH) return;
    int head = blockIdx.y;
    int i = idx >> 7, c = idx & 127;
    float av = aab[(size_t)head*NN*128 + idx];
    float qv = head ? tx[(size_t)(i>>6)*128 + c] : q0[idx];
    float* hr = h3 + (size_t)head*NN*384 + (size_t)i*384;
    hr[c] = av; hr[128+c] = qv; hr[256+c] = av * qv;
}
// fused: logit[i] = lrelu(t2[i,:].W3); then segment softmax per 64-node graph.
__global__ void mlp_tail(const float* __restrict__ t2b, const float* __restrict__ W3,
                         float* __restrict__ out0, float* __restrict__ out1){
    __shared__ float sv[64], se[64];
    int b = blockIdx.x, head = blockIdx.y;
    int tid = threadIdx.x;
    int wid = tid >> 5, lane = tid & 31;
    const float* A = t2b + (size_t)head*NN*128;
    const float* w = W3 + (size_t)head*128;
    float w0 = w[lane], w1 = w[lane+32], w2 = w[lane+64], w3v = w[lane+96];
    #pragma unroll
    for (int rr = 0; rr < 8; rr++){
        int node = wid*8 + rr;
        const float* ar = A + (size_t)(b*64 + node)*128;
        float s = ar[lane]*w0 + ar[lane+32]*w1 + ar[lane+64]*w2 + ar[lane+96]*w3v;
        #pragma unroll
        for (int o = 16; o; o >>= 1) s += __shfl_xor_sync(0xffffffffu, s, o);
        if (lane == 0) sv[node] = lrelu(s);
    }
    __syncthreads();
    float e = 0.f, v = 0.f;
    if (tid < 64){
        v = sv[tid];
        float m = -1e30f;
        #pragma unroll 8
        for (int j = 0; j < 64; j++) m = fmaxf(m, sv[j]);
        e = expf(v - m);
        se[tid] = e;
    }
    __syncthreads();
    if (tid < 64){
        float s = 0.f;
        #pragma unroll 8
        for (int j = 0; j < 64; j++) s += se[j];
        float* out = head ? out1 : out0;
        out[b*64 + tid] = e / s;
    }
}

// ---------------- fused edge softmax + aggregation (race-free normalize) ----------------
__global__ void esm_gather(const int* __restrict__ colPtr, const int* __restrict__ colR,
                           const float* __restrict__ f1, const float* __restrict__ f2,
                           float* __restrict__ Ecol, const float* __restrict__ x,
                           float* __restrict__ agg){
    int node = blockIdx.x*8 + (threadIdx.x >> 5);
    int lane = threadIdx.x & 31;
    if (node >= NN) return;
    int s = colPtr[node], e = colPtr[node+1];
    float f1c = f1[node];
    float mx = -1e30f;
    for (int p = s + lane; p < e; p += 32)
        mx = fmaxf(mx, lrelu(f1c + f2[colR[p]]));
    #pragma unroll
    for (int o = 16; o; o >>= 1) mx = fmaxf(mx, __shfl_xor_sync(0xffffffffu, mx, o));
    float sum = 0.f;
    for (int p = s + lane; p < e; p += 32){
        float ev = expf(lrelu(f1c + f2[colR[p]]) - mx);
        Ecol[p] = ev; sum += ev;
    }
    #pragma unroll
    for (int o = 16; o; o >>= 1) sum += __shfl_xor_sync(0xffffffffu, sum, o);
    float inv = 1.f / sum;
    __syncwarp();
    float a0=0.f, a1=0.f, a2=0.f, a3=0.f;
    for (int p = s; p < e; p++){
        float w = Ecol[p] * inv;          // broadcast read (no write in this loop)
        const float* vr = x + (size_t)colR[p]*HH;
        a0 = fmaf(w, vr[lane],    a0);
        a1 = fmaf(w, vr[lane+32], a1);
        a2 = fmaf(w, vr[lane+64], a2);
        a3 = fmaf(w, vr[lane+96], a3);
    }
    float* vo = agg + (size_t)node*HH;
    vo[lane]=a0; vo[lane+32]=a1; vo[lane+64]=a2; vo[lane+96]=a3;
    for (int p = s + lane; p < e; p += 32) Ecol[p] *= inv;   // normalize in place
}
__global__ void xc_combine(const float* __restrict__ x, const float* __restrict__ g0,
                           const float* __restrict__ g1, float* __restrict__ xc){
    int idx = blockIdx.x*blockDim.x + threadIdx.x;
    if (idx >= NN*HH) return;
    float xv = x[idx];
    xc[idx] = 0.5f * (lrelu(xv + g0[idx]) + lrelu(xv + g1[idx]));
}

// ---------------- finalize: score softmax + stable top-k + pooled outputs ----------------
__global__ void finalize(const float* __restrict__ g1s, const float* __restrict__ g2s,
                         const float* __restrict__ x,
                         int* __restrict__ perm, int* __restrict__ pos,
                         float* __restrict__ out){
    __shared__ float sv[64], se[64], ssc[64];
    __shared__ int sperm[KKC];
    int b = blockIdx.x, tid = threadIdx.x;
    float v = 0.f, e = 0.f;
    if (tid < 64){
        int i = b*64 + tid;
        v = g1s[i] + g2s[i];
        sv[tid] = v;
    }
    __syncthreads();
    if (tid < 64){
        float m = -1e30f;
        #pragma unroll 8
        for (int j = 0; j < 64; j++) m = fmaxf(m, sv[j]);
        e = expf(v - m);
        se[tid] = e;
    }
    __syncthreads();
    if (tid < 64){
        float s = 0.f;
        #pragma unroll 8
        for (int j = 0; j < 64; j++) s += se[j];
        float sc = e / s;
        ssc[tid] = sc;
        int rank = 0;
        for (int j = 0; j < 64; j++){
            float vj = sv[j];
            if (vj > v || (vj == v && j < tid)) rank++;
        }
        int i = b*64 + tid;
        pos[i] = (rank < KKC) ? b*KKC + rank : -1;
        if (rank < KKC){
            int p = b*KKC + rank;
            sperm[rank] = tid;
            perm[p] = i;
            out[OFF_BATCH + p] = (float)b;
            out[OFF_PERM  + p] = (float)i;
        }
    }
    __syncthreads();
    for (int idx = tid; idx < KKC*128; idx += blockDim.x){
        int p = idx >> 7, c = idx & 127;
        int node = sperm[p];
        out[OFF_XOUT + ((size_t)b*KKC + p)*128 + c] =
            x[(size_t)(b*64 + node)*128 + c] * ssc[node];
    }
}

// ---------------- block-diagonal triple product ----------------
__global__ void spgemm_M(const int* __restrict__ rowPtr, const int* __restrict__ rowC,
                         const float* __restrict__ rowEW, const int* __restrict__ rowEp,
                         const float* __restrict__ Ecol, const int* __restrict__ pos,
                         float* __restrict__ Mloc){
    __shared__ float acc[KKC];
    int i = blockIdx.x;
    int tid = threadIdx.x;
    for (int t = tid; t < KKC; t += blockDim.x) acc[t] = 0.f;
    __syncthreads();
    int b52 = (i >> 6) * KKC;
    int s = rowPtr[i], e = rowPtr[i+1];
    int warp = tid >> 5, lane = tid & 31;
    for (int p = s + warp; p < e; p += 4){
        int j = rowC[p]; float ewv = rowEW[p];
        int s2 = rowPtr[j], e2 = rowPtr[j+1];
        for (int q = s2 + lane; q < e2; q += 32){
            int k = pos[rowC[q]];
            if (k >= 0){
                unsigned kk = (unsigned)(k - b52);
                if (kk < KKC) atomicAdd(&acc[kk], ewv * Ecol[rowEp[q]]);
            }
        }
    }
    __syncthreads();
    for (int t = tid; t < KKC; t += blockDim.x) Mloc[(size_t)i*KKC + t] = acc[t];
}
__global__ void a2_full(const int* __restrict__ colPtr, const int* __restrict__ colR,
                        const float* __restrict__ Ecol, const int* __restrict__ perm,
                        const float* __restrict__ Mloc, float* __restrict__ outA2){
    __shared__ float acc[KKC];
    int p = blockIdx.x;
    int tid = threadIdx.x;
    int g = perm[p];
    int base = (g >> 6) * KKC;
    if (tid < KKC){
        float a = 0.f;
        int s = colPtr[g], e = colPtr[g+1];
        for (int q = s; q < e; q++)
            a = fmaf(Ecol[q], Mloc[(size_t)colR[q]*KKC + tid], a);
        acc[tid] = a;
    }
    __syncthreads();
    float* row = outA2 + (size_t)p*NKC;
    for (int t = tid; t < NKC; t += 256){
        unsigned kk = (unsigned)(t - base);
        float v = (kk < KKC) ? acc[kk] : 0.f;
        if (t == p) v = 1.0f;
        row[t] = v;
    }
}

// ---------------- host launcher ----------------
extern "C" void kernel_launch(void* const* d_in, const int* in_sizes, int n_in,
                              void* d_out, int out_size){
    const float* x    = (const float*)d_in[0];
    const int*   ei   = (const int*)  d_in[1];
    const float* ewt  = (const float*)d_in[2];
    const float* tx   = (const float*)d_in[3];
    const float* Wk   = (const float*)d_in[5];
    const float* W1   = (const float*)d_in[6];
    const float* W2   = (const float*)d_in[7];
    const float* W3   = (const float*)d_in[8];
    const float* linW = (const float*)d_in[9];
    float* out = (float*)d_out;

    void* basep = nullptr;
    cudaGetSymbolAddress(&basep, d_scratch);
    float* base = (float*)basep;

    float* deg    = base + O_DEG;
    float* dinv   = base + O_DINV;
    int*   cntc   = (int*)(base + O_CNTC);
    int*   cntr   = (int*)(base + O_CNTR);
    int*   colPtr = (int*)(base + O_COLPTR);
    int*   rowPtr = (int*)(base + O_ROWPTR);
    int*   colCur = (int*)(base + O_COLCUR);
    int*   rowCur = (int*)(base + O_ROWCUR);
    int*   colR   = (int*)(base + O_COLR);
    float* colEW  = base + O_COLEW;
    float* Ecol   = base + O_ECOL;
    int*   rowC   = (int*)(base + O_ROWC);
    float* rowEW  = base + O_ROWEW;
    int*   rowEp  = (int*)(base + O_ROWEP);
    float* aab    = base + O_ABUF;
    float* h3     = base + O_H3;
    float* t1     = base + O_T1;
    float* t2     = base + O_T2;
    float* xq     = base + O_XQ;
    float* tmp    = base + O_TMP;
    float* agg    = base + O_AGG;
    float* g0     = base + O_G0;
    float* g1b    = g0 + (size_t)NN*128;
    float* xc     = base + O_XC;
    float* xq2    = base + O_XQ2;
    float* f1     = base + O_F1;
    float* f2     = base + O_F2;
    float* g1s    = base + O_G1S;
    float* g2s    = base + O_G2S;
    int*   perm   = (int*)(base + O_PERM);
    int*   pos    = (int*)(base + O_POS);
    float* Mloc   = base + O_MLOC;
    float* W1e    = base + O_W1E;

    const int EG = (NEC + 255)/256;
    const size_t S128 = (size_t)NN*128;

    // ---- graph prep (zero + W1 fold fused) ----
    prep0<<<16 + (4*384*256+255)/256, 256>>>(deg, W1, W1e);
    edge_pass1<<<EG,256>>>(ei, ewt, deg, cntc, cntr);
    scan_prep<<<3,1024>>>(cntc, cntr, colPtr, colCur, rowPtr, rowCur, deg, dinv);
    edge_scatter<<<EG,256>>>(ei, ewt, dinv, colCur, rowCur, colR, colEW, rowC, rowEW, rowEp);

    // ---- x_q = hop(hop(x)) ----
    gather_nodes<<<512,256>>>(x,   tmp, colPtr, colR, colEW);
    gather_nodes<<<512,256>>>(tmp, xq,  colPtr, colR, colEW);

    // ---- attention pair (2 heads batched over blockIdx.z) ----
    auto attention_pair = [&](const float* kv, const float* q0, int pairbase,
                              float* out0, float* out1){
        gemm_t<<<dim3(1,64,2),256>>>(kv, Wk + (size_t)pairbase*128*128, aab,
                                     128, 128, 0, 0, (size_t)128*128, S128);
        build_h3<<<dim3(2048,2),256>>>(aab, q0, tx, h3);
        gemm_t<<<dim3(2,64,2),256>>>(h3, W1e + (size_t)pairbase*384*256, t1,
                                     256, 384, 1, (size_t)NN*384, (size_t)384*256, (size_t)NN*256);
        gemm_t<<<dim3(1,64,2),256>>>(t1, W2 + (size_t)pairbase*256*128, t2,
                                     128, 256, 1, (size_t)NN*256, (size_t)256*128, S128);
        mlp_tail<<<dim3(BB,2),256>>>(t2, W3 + (size_t)pairbase*128, out0, out1);
    };

    attention_pair(x, xq, 0, f1, f2);

    // ---- edge softmax + aggregation (fused) ----
    esm_gather<<<512,256>>>(colPtr, colR, f1, f2, Ecol, x, agg);
    gemm_t<<<dim3(1,64,2),256>>>(agg, linW, g0, 128, 128, 0,
                                 0, (size_t)128*128, S128);
    xc_combine<<<2048,256>>>(x, g0, g1b, xc);

    // ---- second round ----
    gather_nodes<<<512,256>>>(xc,  tmp, colPtr, colR, colEW);
    gather_nodes<<<512,256>>>(tmp, xq2, colPtr, colR, colEW);
    attention_pair(xc, xq2, 2, g1s, g2s);

    // ---- score softmax + top-k + pooled outputs ----
    finalize<<<BB,256>>>(g1s, g2s, x, perm, pos, out);

    // ---- A2 = S_p^T (A_d S_p), block-diagonal ----
    spgemm_M<<<NN,128>>>(rowPtr, rowC, rowEW, rowEp, Ecol, pos, Mloc);
    a2_full<<<NKC,256>>>(colPtr, colR, Ecol, perm, Mloc, out + OFF_A2);
}

// round 12
// speedup vs baseline: 1.2772x; 1.2066x over previous
#include <cuda_runtime.h>
#include <cuda_bf16.h>
#include <cstdint>

// ---------------- problem constants ----------------
#define NN   4096
#define HH   128
#define BB   64
#define E0C  131072
#define NEC  135168
#define KKC  52
#define NKC  3328
#define NSLOPE 0.01f

// output layout (floats)
#define OFF_XOUT 0
#define OFF_A2   (NKC*HH)
#define OFF_BATCH (OFF_A2 + (size_t)NKC*NKC)
#define OFF_PERM  (OFF_BATCH + NKC)

// ---------------- scratch layout ----------------
constexpr size_t O_DEG  = 0;                               // NN (zeroed)
constexpr size_t O_AT   = (size_t)NN;                      // 64*4096 (zeroed)
constexpr size_t O_CNTT = O_AT + (size_t)64*4096;          // 64*4096 (zeroed)
constexpr size_t O_DINV = O_CNTT + (size_t)64*4096;        // NN
constexpr size_t O_ST   = O_DINV + NN;                     // 64*4096
constexpr size_t O_U    = O_ST + (size_t)64*4096;          // 64*52*52
constexpr size_t O_ABUF = O_U + (size_t)64*KKC*KKC;        // 2*NN*128
constexpr size_t O_H3   = O_ABUF + (size_t)2*NN*128;       // 2*NN*384
constexpr size_t O_T1   = O_H3   + (size_t)2*NN*384;       // 2*NN*256
constexpr size_t O_T2   = O_T1   + (size_t)2*NN*256;       // 2*NN*128
constexpr size_t O_XQ   = O_T2   + (size_t)2*NN*128;
constexpr size_t O_AGG  = O_XQ   + (size_t)NN*128;
constexpr size_t O_G0   = O_AGG  + (size_t)NN*128;         // 2*NN*128
constexpr size_t O_XC   = O_G0   + (size_t)2*NN*128;
constexpr size_t O_XQ2  = O_XC   + (size_t)NN*128;
constexpr size_t O_F1   = O_XQ2  + (size_t)NN*128;
constexpr size_t O_F2   = O_F1 + NN;
constexpr size_t O_G1S  = O_F2 + NN;
constexpr size_t O_G2S  = O_G1S + NN;
constexpr size_t O_PERM = O_G2S + NN;                      // NKC ints
constexpr size_t O_W1E  = O_PERM + NKC;                    // 4*384*256
constexpr size_t SCRATCH_ELEMS = O_W1E + (size_t)4*384*256;

__device__ __align__(16) float d_scratch[SCRATCH_ELEMS];

__device__ __forceinline__ float lrelu(float v){ return v >= 0.f ? v : NSLOPE*v; }

// packed fp32x2 fma (Blackwell)
#define FMA2(accv, av, bv) \
    asm("fma.rn.f32x2 %0, %1, %2, %3;" : "=l"(accv) : "l"(av), "l"(bv), "l"(accv))

union UF2 { unsigned long long u; float2 f; };

// ---------------- prep0: zero deg+AT+CNT, build folded W1 ----------------
__global__ void prep0(float* zbase, const float* __restrict__ W1, float* __restrict__ W1e){
    int b = blockIdx.x;
    const int ZN = NN + 2*64*4096;   // deg + AT + CNTT contiguous
    if (b < 64){
        for (int i = b*256 + threadIdx.x; i < ZN; i += 64*256) zbase[i] = 0.f;
        return;
    }
    int idx = (b-64)*256 + threadIdx.x;
    if (idx >= 4*384*256) return;
    int h = idx / (384*256);
    int rem = idx - h*(384*256);
    int r = rem >> 8, c = rem & 255;
    const float* Wh = W1 + (size_t)h*512*256;
    float v;
    if (r < 128)       v = Wh[(size_t)r*256 + c] + Wh[(size_t)(256+r)*256 + c];
    else if (r < 256)  v = Wh[(size_t)r*256 + c] - Wh[(size_t)(r+128)*256 + c];
    else               v = Wh[(size_t)(r+128)*256 + c];
    W1e[idx] = v;
}

// ---------------- graph prep ----------------
__global__ void edge_pass1(const int* __restrict__ ei, const float* __restrict__ w,
                           float* deg){
    int e = blockIdx.x*blockDim.x + threadIdx.x;
    if (e >= NEC) return;
    int c; float wv;
    if (e < E0C){ c = ei[E0C + e]; wv = w[e]; }
    else        { c = e - E0C; wv = 1.f; }
    atomicAdd(&deg[c], wv);
}
__global__ void compute_dinv(const float* deg, float* dinv){
    int i = blockIdx.x*blockDim.x + threadIdx.x;
    if (i < NN) dinv[i] = rsqrtf(fmaxf(deg[i], 1e-12f));
}
// dense per-graph transposed adjacency + edge-count (duplicates accumulate)
__global__ void dense_build(const int* __restrict__ ei, const float* __restrict__ w,
                            const float* __restrict__ dinv,
                            float* __restrict__ AT, float* __restrict__ CNT){
    int e = blockIdx.x*blockDim.x + threadIdx.x;
    if (e >= NEC) return;
    int r, c; float wv;
    if (e < E0C){ r = ei[e]; c = ei[E0C + e]; wv = w[e]; }
    else        { r = c = e - E0C; wv = 1.f; }
    float ewv = dinv[r]*wv*dinv[c];
    int idx = (r >> 6)*4096 + (c & 63)*64 + (r & 63);
    atomicAdd(&AT[idx], ewv);
    atomicAdd(&CNT[idx], 1.f);
}

// ---------------- double hop, dense per graph: out = A^T (A^T in) ----------------
__global__ __launch_bounds__(256) void hop2_dense(const float* __restrict__ xin,
                                                  float* __restrict__ xout,
                                                  const float* __restrict__ AT){
    extern __shared__ float sm[];
    float* sA = sm;              // 64*65
    float* sX = sm + 4160;       // 64*132
    float* sY = sX + 8448;       // 64*132
    int b = blockIdx.x, tid = threadIdx.x;
    for (int i = tid; i < 4096; i += 256)
        sA[(i>>6)*65 + (i&63)] = AT[(size_t)b*4096 + i];
    for (int i = tid; i < 8192; i += 256){
        int r = i >> 7, h = i & 127;
        sX[r*132 + h] = xin[(size_t)(b*64+r)*128 + h];
    }
    __syncthreads();
    const int tc = tid >> 5;
    const int th = (tid & 31) << 2;
    // pass 1: Y = A^T X
    {
        unsigned long long acc[8][2];
        #pragma unroll
        for (int cc = 0; cc < 8; cc++){ acc[cc][0]=0ull; acc[cc][1]=0ull; }
        for (int r = 0; r < 64; r++){
            ulonglong2 xv = *(const ulonglong2*)&sX[r*132 + th];
            #pragma unroll
            for (int cc = 0; cc < 8; cc++){
                UF2 ap; float a = sA[(tc*8+cc)*65 + r];
                ap.f = make_float2(a, a);
                FMA2(acc[cc][0], ap.u, xv.x);
                FMA2(acc[cc][1], ap.u, xv.y);
            }
        }
        #pragma unroll
        for (int cc = 0; cc < 8; cc++){
            ulonglong2 o; o.x = acc[cc][0]; o.y = acc[cc][1];
            *(ulonglong2*)&sY[(tc*8+cc)*132 + th] = o;
        }
    }
    __syncthreads();
    // pass 2: out = A^T Y
    {
        unsigned long long acc[8][2];
        #pragma unroll
        for (int cc = 0; cc < 8; cc++){ acc[cc][0]=0ull; acc[cc][1]=0ull; }
        for (int r = 0; r < 64; r++){
            ulonglong2 xv = *(const ulonglong2*)&sY[r*132 + th];
            #pragma unroll
            for (int cc = 0; cc < 8; cc++){
                UF2 ap; float a = sA[(tc*8+cc)*65 + r];
                ap.f = make_float2(a, a);
                FMA2(acc[cc][0], ap.u, xv.x);
                FMA2(acc[cc][1], ap.u, xv.y);
            }
        }
        #pragma unroll
        for (int cc = 0; cc < 8; cc++){
            ulonglong2 o; o.x = acc[cc][0]; o.y = acc[cc][1];
            *(ulonglong2*)&xout[(size_t)(b*64 + tc*8+cc)*128 + th] = o;
        }
    }
}

// ---------------- packed fp32x2 GEMM (64x64 tile, z-batched) — proven R5 version ----------------
__global__ __launch_bounds__(256) void gemm64p(
        const float* __restrict__ A, const float* __restrict__ B,
        float* __restrict__ C, int M, int N, int K, int leaky,
        size_t Astr, size_t Bstr, size_t Cstr){
    A += blockIdx.z*Astr; B += blockIdx.z*Bstr; C += blockIdx.z*Cstr;
    __shared__ __align__(16) float AsD[16][136];
    __shared__ __align__(16) float Bs[16][68];
    const int tid = threadIdx.x;
    const int tn = tid & 15;
    const int tm = tid >> 4;
    const int row0 = blockIdx.y*64;
    const int col0 = blockIdx.x*64;
    const int arow = tid >> 2;
    const int acol = (tid & 3) << 2;
    const int brow = tid >> 4;
    const int bcol = (tid & 15) << 2;
    unsigned long long acc[4][2];
    #pragma unroll
    for (int i = 0; i < 4; i++){ acc[i][0] = 0ull; acc[i][1] = 0ull; }
    for (int k0 = 0; k0 < K; k0 += 16){
        float4 av = *(const float4*)(A + (size_t)(row0+arow)*K + k0 + acol);
        *(float2*)&AsD[acol+0][2*arow] = make_float2(av.x, av.x);
        *(float2*)&AsD[acol+1][2*arow] = make_float2(av.y, av.y);
        *(float2*)&AsD[acol+2][2*arow] = make_float2(av.z, av.z);
        *(float2*)&AsD[acol+3][2*arow] = make_float2(av.w, av.w);
        float4 bv = *(const float4*)(B + (size_t)(k0+brow)*N + col0 + bcol);
        *(float4*)&Bs[brow][bcol] = bv;
        __syncthreads();
        #pragma unroll
        for (int k = 0; k < 16; k++){
            ulonglong2 aD0 = *reinterpret_cast<const ulonglong2*>(&AsD[k][tm*8]);
            ulonglong2 aD1 = *reinterpret_cast<const ulonglong2*>(&AsD[k][tm*8+4]);
            ulonglong2 bp  = *reinterpret_cast<const ulonglong2*>(&Bs[k][tn*4]);
            FMA2(acc[0][0], aD0.x, bp.x); FMA2(acc[0][1], aD0.x, bp.y);
            FMA2(acc[1][0], aD0.y, bp.x); FMA2(acc[1][1], aD0.y, bp.y);
            FMA2(acc[2][0], aD1.x, bp.x); FMA2(acc[2][1], aD1.x, bp.y);
            FMA2(acc[3][0], aD1.y, bp.x); FMA2(acc[3][1], aD1.y, bp.y);
        }
        __syncthreads();
    }
    #pragma unroll
    for (int i = 0; i < 4; i++){
        int r = row0 + (tm<<2) + i;
        #pragma unroll
        for (int jp = 0; jp < 2; jp++){
            union { unsigned long long u; float2 f; } cv;
            cv.u = acc[i][jp];
            float2 v = cv.f;
            if (leaky){
                v.x = v.x >= 0.f ? v.x : NSLOPE*v.x;
                v.y = v.y >= 0.f ? v.y : NSLOPE*v.y;
            }
            *(float2*)(C + (size_t)r*N + col0 + (tn<<2) + jp*2) = v;
        }
    }
}

// ---------------- attention helpers ----------------
// h3 = [a, q, a*q]  (head 1 reads target_x directly)
__global__ void build_h3(const float* __restrict__ aab, const float* __restrict__ q0,
                         const float* __restrict__ tx, float* __restrict__ h3){
    int idx = blockIdx.x*blockDim.x + threadIdx.x;
    if (idx >= NN*HH) return;
    int head = blockIdx.y;
    int i = idx >> 7, c = idx & 127;
    float av = aab[(size_t)head*NN*128 + idx];
    float qv = head ? tx[(size_t)(i>>6)*128 + c] : q0[idx];
    float* hr = h3 + (size_t)head*NN*384 + (size_t)i*384;
    hr[c] = av; hr[128+c] = qv; hr[256+c] = av * qv;
}
// fused: logit = lrelu(t2.W3); segment softmax per graph.
__global__ void mlp_tail(const float* __restrict__ t2b, const float* __restrict__ W3,
                         float* __restrict__ out0, float* __restrict__ out1){
    __shared__ float sv[64], se[64];
    int b = blockIdx.x, head = blockIdx.y;
    int tid = threadIdx.x;
    int wid = tid >> 5, lane = tid & 31;
    const float* A = t2b + (size_t)head*NN*128;
    const float* w = W3 + (size_t)head*128;
    float w0 = w[lane], w1 = w[lane+32], w2 = w[lane+64], w3v = w[lane+96];
    #pragma unroll
    for (int rr = 0; rr < 8; rr++){
        int node = wid*8 + rr;
        const float* ar = A + (size_t)(b*64 + node)*128;
        float s = ar[lane]*w0 + ar[lane+32]*w1 + ar[lane+64]*w2 + ar[lane+96]*w3v;
        #pragma unroll
        for (int o = 16; o; o >>= 1) s += __shfl_xor_sync(0xffffffffu, s, o);
        if (lane == 0) sv[node] = lrelu(s);
    }
    __syncthreads();
    float e = 0.f, v = 0.f;
    if (tid < 64){
        v = sv[tid];
        float m = -1e30f;
        #pragma unroll 8
        for (int j = 0; j < 64; j++) m = fmaxf(m, sv[j]);
        e = expf(v - m);
        se[tid] = e;
    }
    __syncthreads();
    if (tid < 64){
        float s = 0.f;
        #pragma unroll 8
        for (int j = 0; j < 64; j++) s += se[j];
        float* out = head ? out1 : out0;
        out[b*64 + tid] = e / s;
    }
}

// ---------------- dense edge softmax (with multiplicity) + agg = S^T X ----------------
__global__ __launch_bounds__(256) void esm_agg(const float* __restrict__ CNT,
                                               const float* __restrict__ f1,
                                               const float* __restrict__ f2,
                                               const float* __restrict__ x,
                                               float* __restrict__ STg,
                                               float* __restrict__ agg){
    extern __shared__ float sm[];
    float* sCT = sm;             // 4160
    float* sST = sm + 4160;      // 4160
    float* sX  = sm + 8320;      // 8448
    float* sF1 = sm + 16768;     // 64
    float* sF2 = sm + 16832;     // 64
    int b = blockIdx.x, tid = threadIdx.x;
    for (int i = tid; i < 4096; i += 256)
        sCT[(i>>6)*65 + (i&63)] = CNT[(size_t)b*4096 + i];
    for (int i = tid; i < 8192; i += 256){
        int r = i >> 7, h = i & 127;
        sX[r*132 + h] = x[(size_t)(b*64+r)*128 + h];
    }
    if (tid < 64) sF1[tid] = f1[b*64 + tid];
    else if (tid < 128) sF2[tid-64] = f2[b*64 + tid - 64];
    __syncthreads();
    if (tid < 64){
        int c = tid; float f1c = sF1[c];
        float m = -1e30f;
        for (int r = 0; r < 64; r++)
            if (sCT[c*65+r] > 0.5f)
                m = fmaxf(m, lrelu(f1c + sF2[r]));
        float den = 0.f;
        for (int r = 0; r < 64; r++){
            float cv = sCT[c*65+r];
            float ev = 0.f;
            if (cv > 0.5f){
                ev = cv * expf(lrelu(f1c + sF2[r]) - m);
                den += ev;
            }
            sST[c*65+r] = ev;
        }
        float inv = 1.f / den;
        for (int r = 0; r < 64; r++) sST[c*65+r] *= inv;
    }
    __syncthreads();
    for (int i = tid; i < 4096; i += 256)
        STg[(size_t)b*4096 + i] = sST[(i>>6)*65 + (i&63)];
    const int tc = tid >> 5;
    const int th = (tid & 31) << 2;
    unsigned long long acc[8][2];
    #pragma unroll
    for (int cc = 0; cc < 8; cc++){ acc[cc][0]=0ull; acc[cc][1]=0ull; }
    for (int r = 0; r < 64; r++){
        ulonglong2 xv = *(const ulonglong2*)&sX[r*132 + th];
        #pragma unroll
        for (int cc = 0; cc < 8; cc++){
            UF2 ap; float a = sST[(tc*8+cc)*65 + r];
            ap.f = make_float2(a, a);
            FMA2(acc[cc][0], ap.u, xv.x);
            FMA2(acc[cc][1], ap.u, xv.y);
        }
    }
    #pragma unroll
    for (int cc = 0; cc < 8; cc++){
        ulonglong2 o; o.x = acc[cc][0]; o.y = acc[cc][1];
        *(ulonglong2*)&agg[(size_t)(b*64 + tc*8+cc)*128 + th] = o;
    }
}
__global__ void xc_combine(const float* __restrict__ x, const float* __restrict__ g0,
                           const float* __restrict__ g1, float* __restrict__ xc){
    int idx = blockIdx.x*blockDim.x + threadIdx.x;
    if (idx >= NN*HH) return;
    float xv = x[idx];
    xc[idx] = 0.5f * (lrelu(xv + g0[idx]) + lrelu(xv + g1[idx]));
}

// ---------------- finalize: score softmax + stable top-k + pooled outputs ----------------
__global__ void finalize(const float* __restrict__ g1s, const float* __restrict__ g2s,
                         const float* __restrict__ x,
                         int* __restrict__ perm, float* __restrict__ out){
    __shared__ float sv[64], se[64], ssc[64];
    __shared__ int sperm[KKC];
    int b = blockIdx.x, tid = threadIdx.x;
    float v = 0.f, e = 0.f;
    if (tid < 64){
        int i = b*64 + tid;
        v = g1s[i] + g2s[i];
        sv[tid] = v;
    }
    __syncthreads();
    if (tid < 64){
        float m = -1e30f;
        #pragma unroll 8
        for (int j = 0; j < 64; j++) m = fmaxf(m, sv[j]);
        e = expf(v - m);
        se[tid] = e;
    }
    __syncthreads();
    if (tid < 64){
        float s = 0.f;
        #pragma unroll 8
        for (int j = 0; j < 64; j++) s += se[j];
        float sc = e / s;
        ssc[tid] = sc;
        int rank = 0;
        for (int j = 0; j < 64; j++){
            float vj = sv[j];
            if (vj > v || (vj == v && j < tid)) rank++;
        }
        if (rank < KKC){
            int p = b*KKC + rank;
            sperm[rank] = tid;
            perm[p] = b*64 + tid;
            out[OFF_BATCH + p] = (float)b;
            out[OFF_PERM  + p] = (float)(b*64 + tid);
        }
    }
    __syncthreads();
    for (int idx = tid; idx < KKC*128; idx += blockDim.x){
        int p = idx >> 7, c = idx & 127;
        int node = sperm[p];
        out[OFF_XOUT + ((size_t)b*KKC + p)*128 + c] =
            x[(size_t)(b*64 + node)*128 + c] * ssc[node];
    }
}

// ---------------- dense triple product: U = S_p^T (A S_p) per graph ----------------
__global__ __launch_bounds__(256) void a2_dense(const float* __restrict__ AT,
                                                const float* __restrict__ STg,
                                                const int* __restrict__ perm,
                                                float* __restrict__ U){
    __shared__ float sA[4160], sS[4160], sT[64*53];
    __shared__ int sp[KKC];
    int b = blockIdx.x, tid = threadIdx.x;
    for (int i = tid; i < 4096; i += 256){
        int o = (i>>6)*65 + (i&63);
        sA[o] = AT[(size_t)b*4096 + i];
        sS[o] = STg[(size_t)b*4096 + i];
    }
    if (tid < KKC) sp[tid] = perm[b*KKC + tid] & 63;
    __syncthreads();
    // T[r][j] = sum_k A[r][k]*S[k][pj] = sum_k sA[k][r]*sS[pj][k]
    {
        int r = tid & 63;
        for (int j = tid >> 6; j < KKC; j += 4){
            int pj = sp[j];
            float acc = 0.f;
            for (int k = 0; k < 64; k++)
                acc = fmaf(sA[k*65 + r], sS[pj*65 + k], acc);
            sT[r*53 + j] = acc;
        }
    }
    __syncthreads();
    // U[i][j] = sum_r S[r][pi]*T[r][j] = sum_r sS[pi][r]*T[r][j]
    {
        int i = tid & 63;
        if (i < KKC){
            int pi = sp[i];
            for (int j = tid >> 6; j < KKC; j += 4){
                float acc = 0.f;
                for (int r = 0; r < 64; r++)
                    acc = fmaf(sS[pi*65 + r], sT[r*53 + j], acc);
                U[(size_t)b*(KKC*KKC) + i*KKC + j] = acc;
            }
        }
    }
}
// write full A2 rows (zero fill + band + unit diag)
__global__ void a2_write(const float* __restrict__ U, float* __restrict__ outA2){
    __shared__ float sU[KKC];
    int p = blockIdx.x, tid = threadIdx.x;
    int b = p / KKC;
    int li = p - b*KKC;
    if (tid < KKC) sU[tid] = U[(size_t)b*(KKC*KKC) + li*KKC + tid];
    __syncthreads();
    int base = b*KKC;
    float* row = outA2 + (size_t)p*NKC;
    for (int t = tid; t < NKC; t += 256){
        unsigned kk = (unsigned)(t - base);
        float v = (kk < (unsigned)KKC) ? sU[kk] : 0.f;
        if (t == p) v = 1.0f;
        row[t] = v;
    }
}

// ---------------- host launcher ----------------
extern "C" void kernel_launch(void* const* d_in, const int* in_sizes, int n_in,
                              void* d_out, int out_size){
    const float* x    = (const float*)d_in[0];
    const int*   ei   = (const int*)  d_in[1];
    const float* ewt  = (const float*)d_in[2];
    const float* tx   = (const float*)d_in[3];
    const float* Wk   = (const float*)d_in[5];
    const float* W1   = (const float*)d_in[6];
    const float* W2   = (const float*)d_in[7];
    const float* W3   = (const float*)d_in[8];
    const float* linW = (const float*)d_in[9];
    float* out = (float*)d_out;

    void* basep = nullptr;
    cudaGetSymbolAddress(&basep, d_scratch);
    float* base = (float*)basep;

    float* deg   = base + O_DEG;
    float* AT    = base + O_AT;
    float* CNT   = base + O_CNTT;
    float* dinv  = base + O_DINV;
    float* STg   = base + O_ST;
    float* U     = base + O_U;
    float* aab   = base + O_ABUF;
    float* h3    = base + O_H3;
    float* t1    = base + O_T1;
    float* t2    = base + O_T2;
    float* xq    = base + O_XQ;
    float* agg   = base + O_AGG;
    float* g0    = base + O_G0;
    float* g1b   = g0 + (size_t)NN*128;
    float* xc    = base + O_XC;
    float* xq2   = base + O_XQ2;
    float* f1    = base + O_F1;
    float* f2    = base + O_F2;
    float* g1s   = base + O_G1S;
    float* g2s   = base + O_G2S;
    int*   perm  = (int*)(base + O_PERM);
    float* W1e   = base + O_W1E;

    static bool attr_done = false;
    if (!attr_done){
        cudaFuncSetAttribute(hop2_dense, cudaFuncAttributeMaxDynamicSharedMemorySize, 84224);
        cudaFuncSetAttribute(esm_agg,    cudaFuncAttributeMaxDynamicSharedMemorySize, 67584);
        attr_done = true;
    }

    const int EG = (NEC + 255)/256;
    const size_t S128 = (size_t)NN*128;

    // ---- graph prep ----
    prep0<<<64 + (4*384*256+255)/256, 256>>>(base, W1, W1e);
    edge_pass1<<<EG,256>>>(ei, ewt, deg);
    compute_dinv<<<16,256>>>(deg, dinv);
    dense_build<<<EG,256>>>(ei, ewt, dinv, AT, CNT);

    // ---- x_q = hop(hop(x)) ----
    hop2_dense<<<BB,256,84224>>>(x, xq, AT);

    // ---- attention pair (2 heads batched over blockIdx.z) ----
    auto attention_pair = [&](const float* kv, const float* q0, int pairbase,
                              float* out0, float* out1){
        gemm64p<<<dim3(2,64,2),256>>>(kv, Wk + (size_t)pairbase*128*128, aab,
                                      NN, 128, 128, 0, 0, (size_t)128*128, S128);
        build_h3<<<dim3(2048,2),256>>>(aab, q0, tx, h3);
        gemm64p<<<dim3(4,64,2),256>>>(h3, W1e + (size_t)pairbase*384*256, t1,
                                      NN, 256, 384, 1, (size_t)NN*384, (size_t)384*256, (size_t)NN*256);
        gemm64p<<<dim3(2,64,2),256>>>(t1, W2 + (size_t)pairbase*256*128, t2,
                                      NN, 128, 256, 1, (size_t)NN*256, (size_t)256*128, S128);
        mlp_tail<<<dim3(BB,2),256>>>(t2, W3 + (size_t)pairbase*128, out0, out1);
    };

    attention_pair(x, xq, 0, f1, f2);

    // ---- dense edge softmax + aggregation ----
    esm_agg<<<BB,256,67584>>>(CNT, f1, f2, x, STg, agg);
    gemm64p<<<dim3(2,64,2),256>>>(agg, linW, g0, NN, 128, 128, 0,
                                  0, (size_t)128*128, S128);
    xc_combine<<<2048,256>>>(x, g0, g1b, xc);

    // ---- second round ----
    hop2_dense<<<BB,256,84224>>>(xc, xq2, AT);
    attention_pair(xc, xq2, 2, g1s, g2s);

    // ---- score softmax + top-k + pooled outputs ----
    finalize<<<BB,256>>>(g1s, g2s, x, perm, out);

    // ---- A2 = S_p^T (A_d S_p) dense per graph ----
    a2_dense<<<BB,256>>>(AT, STg, perm, U);
    a2_write<<<NKC,256>>>(U, out + OFF_A2);
}

// round 15
// speedup vs baseline: 1.3410x; 1.0500x over previous
#include <cuda_runtime.h>
#include <cuda_bf16.h>
#include <cstdint>

// ---------------- problem constants ----------------
#define NN   4096
#define HH   128
#define BB   64
#define E0C  131072
#define NEC  135168
#define KKC  52
#define NKC  3328
#define NSLOPE 0.01f

// output layout (floats)
#define OFF_XOUT 0
#define OFF_A2   (NKC*HH)
#define OFF_BATCH (OFF_A2 + (size_t)NKC*NKC)
#define OFF_PERM  (OFF_BATCH + NKC)

// ---------------- scratch layout ----------------
constexpr size_t O_DEG  = 0;                               // NN (zeroed)
constexpr size_t O_AT   = (size_t)NN;                      // 64*4096 (zeroed)
constexpr size_t O_CNTT = O_AT + (size_t)64*4096;          // 64*4096 (zeroed)
constexpr size_t O_DINV = O_CNTT + (size_t)64*4096;        // NN
constexpr size_t O_ST   = O_DINV + NN;                     // 64*4096
constexpr size_t O_U    = O_ST + (size_t)64*4096;          // 64*52*52
constexpr size_t O_H3   = O_U + (size_t)64*KKC*KKC;        // 2*NN*384
constexpr size_t O_T1   = O_H3   + (size_t)2*NN*384;       // 2*NN*256
constexpr size_t O_T2   = O_T1   + (size_t)2*NN*256;       // 2*NN*128
constexpr size_t O_XQ   = O_T2   + (size_t)2*NN*128;
constexpr size_t O_AGG  = O_XQ   + (size_t)NN*128;
constexpr size_t O_G0   = O_AGG  + (size_t)NN*128;         // 2*NN*128
constexpr size_t O_XC   = O_G0   + (size_t)2*NN*128;
constexpr size_t O_XQ2  = O_XC   + (size_t)NN*128;
constexpr size_t O_F1   = O_XQ2  + (size_t)NN*128;
constexpr size_t O_F2   = O_F1 + NN;
constexpr size_t O_G1S  = O_F2 + NN;
constexpr size_t O_G2S  = O_G1S + NN;
constexpr size_t O_PERM = O_G2S + NN;                      // NKC ints
constexpr size_t O_W1E  = O_PERM + NKC;                    // 4*384*256
constexpr size_t SCRATCH_ELEMS = O_W1E + (size_t)4*384*256;

__device__ __align__(16) float d_scratch[SCRATCH_ELEMS];

__device__ __forceinline__ float lrelu(float v){ return v >= 0.f ? v : NSLOPE*v; }

// packed fp32x2 fma (Blackwell)
#define FMA2(accv, av, bv) \
    asm("fma.rn.f32x2 %0, %1, %2, %3;" : "=l"(accv) : "l"(av), "l"(bv), "l"(accv))

union UF2 { unsigned long long u; float2 f; };

// ---------------- prep0: zero deg+AT+CNT (float4), build folded W1 ----------------
__global__ void prep0(float4* zbase4, const float* __restrict__ W1, float* __restrict__ W1e){
    int b = blockIdx.x;
    const int ZN4 = (NN + 2*64*4096) / 4;
    if (b < 32){
        float4 z = make_float4(0.f,0.f,0.f,0.f);
        for (int i = b*256 + threadIdx.x; i < ZN4; i += 32*256) zbase4[i] = z;
        return;
    }
    int idx = (b-32)*256 + threadIdx.x;
    if (idx >= 4*384*256) return;
    int h = idx / (384*256);
    int rem = idx - h*(384*256);
    int r = rem >> 8, c = rem & 255;
    const float* Wh = W1 + (size_t)h*512*256;
    float v;
    if (r < 128)       v = Wh[(size_t)r*256 + c] + Wh[(size_t)(256+r)*256 + c];
    else if (r < 256)  v = Wh[(size_t)r*256 + c] - Wh[(size_t)(r+128)*256 + c];
    else               v = Wh[(size_t)(r+128)*256 + c];
    W1e[idx] = v;
}

// ---------------- graph prep ----------------
__global__ void edge_pass1(const int* __restrict__ ei, const float* __restrict__ w,
                           float* deg){
    int e = blockIdx.x*blockDim.x + threadIdx.x;
    if (e >= NEC) return;
    int c; float wv;
    if (e < E0C){ c = ei[E0C + e]; wv = w[e]; }
    else        { c = e - E0C; wv = 1.f; }
    atomicAdd(&deg[c], wv);
}
__global__ void compute_dinv(const float* deg, float* dinv){
    int i = blockIdx.x*blockDim.x + threadIdx.x;
    if (i < NN) dinv[i] = rsqrtf(fmaxf(deg[i], 1e-12f));
}
// dense per-graph transposed adjacency + edge-count (duplicates accumulate)
__global__ void dense_build(const int* __restrict__ ei, const float* __restrict__ w,
                            const float* __restrict__ dinv,
                            float* __restrict__ AT, float* __restrict__ CNT){
    int e = blockIdx.x*blockDim.x + threadIdx.x;
    if (e >= NEC) return;
    int r, c; float wv;
    if (e < E0C){ r = ei[e]; c = ei[E0C + e]; wv = w[e]; }
    else        { r = c = e - E0C; wv = 1.f; }
    float ewv = dinv[r]*wv*dinv[c];
    int idx = (r >> 6)*4096 + (c & 63)*64 + (r & 63);
    atomicAdd(&AT[idx], ewv);
    atomicAdd(&CNT[idx], 1.f);
}

// ---------------- double hop, dense per graph: out = A^T (A^T in) ----------------
__global__ __launch_bounds__(256) void hop2_dense(const float* __restrict__ xin,
                                                  float* __restrict__ xout,
                                                  const float* __restrict__ AT){
    extern __shared__ float sm[];
    float* sA = sm;              // 64*65
    float* sX = sm + 4160;       // 64*132
    float* sY = sX + 8448;       // 64*132
    int b = blockIdx.x, tid = threadIdx.x;
    for (int i = tid; i < 4096; i += 256)
        sA[(i>>6)*65 + (i&63)] = AT[(size_t)b*4096 + i];
    for (int i = tid; i < 8192; i += 256){
        int r = i >> 7, h = i & 127;
        sX[r*132 + h] = xin[(size_t)(b*64+r)*128 + h];
    }
    __syncthreads();
    const int tc = tid >> 5;
    const int th = (tid & 31) << 2;
    {
        unsigned long long acc[8][2];
        #pragma unroll
        for (int cc = 0; cc < 8; cc++){ acc[cc][0]=0ull; acc[cc][1]=0ull; }
        for (int r = 0; r < 64; r++){
            ulonglong2 xv = *(const ulonglong2*)&sX[r*132 + th];
            #pragma unroll
            for (int cc = 0; cc < 8; cc++){
                UF2 ap; float a = sA[(tc*8+cc)*65 + r];
                ap.f = make_float2(a, a);
                FMA2(acc[cc][0], ap.u, xv.x);
                FMA2(acc[cc][1], ap.u, xv.y);
            }
        }
        #pragma unroll
        for (int cc = 0; cc < 8; cc++){
            ulonglong2 o; o.x = acc[cc][0]; o.y = acc[cc][1];
            *(ulonglong2*)&sY[(tc*8+cc)*132 + th] = o;
        }
    }
    __syncthreads();
    {
        unsigned long long acc[8][2];
        #pragma unroll
        for (int cc = 0; cc < 8; cc++){ acc[cc][0]=0ull; acc[cc][1]=0ull; }
        for (int r = 0; r < 64; r++){
            ulonglong2 xv = *(const ulonglong2*)&sY[r*132 + th];
            #pragma unroll
            for (int cc = 0; cc < 8; cc++){
                UF2 ap; float a = sA[(tc*8+cc)*65 + r];
                ap.f = make_float2(a, a);
                FMA2(acc[cc][0], ap.u, xv.x);
                FMA2(acc[cc][1], ap.u, xv.y);
            }
        }
        #pragma unroll
        for (int cc = 0; cc < 8; cc++){
            ulonglong2 o; o.x = acc[cc][0]; o.y = acc[cc][1];
            *(ulonglong2*)&xout[(size_t)(b*64 + tc*8+cc)*128 + th] = o;
        }
    }
}

// ---------------- double-buffered packed fp32x2 GEMM (64x64 tile, z-batched) ----------------
__global__ __launch_bounds__(256) void gemm64p(
        const float* __restrict__ A, const float* __restrict__ B,
        float* __restrict__ C, int N, int K, int leaky,
        size_t Astr, size_t Bstr, size_t Cstr){
    A += blockIdx.z*Astr; B += blockIdx.z*Bstr; C += blockIdx.z*Cstr;
    __shared__ __align__(16) float AsD[2][16*136];
    __shared__ __align__(16) float Bs[2][16*68];
    const int tid = threadIdx.x;
    const int tn = tid & 15;
    const int tm = tid >> 4;
    const int row0 = blockIdx.y*64;
    const int col0 = blockIdx.x*64;
    const int arow = tid >> 2;
    const int acol = (tid & 3) << 2;
    const int brow = tid >> 4;
    const int bcol = (tid & 15) << 2;
    const float* Ap = A + (size_t)(row0+arow)*K + acol;
    const float* Bp = B + (size_t)brow*N + col0 + bcol;
    unsigned long long acc[4][2];
    #pragma unroll
    for (int i = 0; i < 4; i++){ acc[i][0] = 0ull; acc[i][1] = 0ull; }
    const int nk = K >> 4;
    float4 av = *(const float4*)Ap;
    float4 bv = *(const float4*)Bp;
    {
        float* Ad = AsD[0];
        *(float2*)&Ad[(acol+0)*136 + 2*arow] = make_float2(av.x, av.x);
        *(float2*)&Ad[(acol+1)*136 + 2*arow] = make_float2(av.y, av.y);
        *(float2*)&Ad[(acol+2)*136 + 2*arow] = make_float2(av.z, av.z);
        *(float2*)&Ad[(acol+3)*136 + 2*arow] = make_float2(av.w, av.w);
        *(float4*)&Bs[0][brow*68 + bcol] = bv;
    }
    __syncthreads();
    for (int t = 0; t < nk; t++){
        int cur = t & 1;
        if (t+1 < nk){
            av = *(const float4*)(Ap + (t+1)*16);
            bv = *(const float4*)(Bp + (size_t)(t+1)*16*N);
        }
        const float* Ad = AsD[cur];
        const float* Bb = Bs[cur];
        #pragma unroll
        for (int k = 0; k < 16; k++){
            ulonglong2 aD0 = *reinterpret_cast<const ulonglong2*>(&Ad[k*136 + tm*8]);
            ulonglong2 aD1 = *reinterpret_cast<const ulonglong2*>(&Ad[k*136 + tm*8 + 4]);
            ulonglong2 bp  = *reinterpret_cast<const ulonglong2*>(&Bb[k*68 + tn*4]);
            FMA2(acc[0][0], aD0.x, bp.x); FMA2(acc[0][1], aD0.x, bp.y);
            FMA2(acc[1][0], aD0.y, bp.x); FMA2(acc[1][1], aD0.y, bp.y);
            FMA2(acc[2][0], aD1.x, bp.x); FMA2(acc[2][1], aD1.x, bp.y);
            FMA2(acc[3][0], aD1.y, bp.x); FMA2(acc[3][1], aD1.y, bp.y);
        }
        if (t+1 < nk){
            float* Ad2 = AsD[cur^1];
            *(float2*)&Ad2[(acol+0)*136 + 2*arow] = make_float2(av.x, av.x);
            *(float2*)&Ad2[(acol+1)*136 + 2*arow] = make_float2(av.y, av.y);
            *(float2*)&Ad2[(acol+2)*136 + 2*arow] = make_float2(av.z, av.z);
            *(float2*)&Ad2[(acol+3)*136 + 2*arow] = make_float2(av.w, av.w);
            *(float4*)&Bs[cur^1][brow*68 + bcol] = bv;
        }
        __syncthreads();
    }
    #pragma unroll
    for (int i = 0; i < 4; i++){
        int r = row0 + (tm<<2) + i;
        #pragma unroll
        for (int jp = 0; jp < 2; jp++){
            UF2 cv; cv.u = acc[i][jp];
            float2 v = cv.f;
            if (leaky){
                v.x = v.x >= 0.f ? v.x : NSLOPE*v.x;
                v.y = v.y >= 0.f ? v.y : NSLOPE*v.y;
            }
            *(float2*)(C + (size_t)r*N + col0 + (tn<<2) + jp*2) = v;
        }
    }
}

// ---------------- Wk GEMM with fused h3 epilogue ----------------
// a = kv @ Wk[head]; h3[head] row r gets [a, q, a*q] (q = xq or tx per head).
__global__ __launch_bounds__(256) void gemm_h3(
        const float* __restrict__ kv, const float* __restrict__ Wk,
        const float* __restrict__ q0, const float* __restrict__ tx,
        float* __restrict__ h3){
    const int head = blockIdx.z;
    const float* B = Wk + (size_t)head*128*128;
    __shared__ __align__(16) float AsD[2][16*136];
    __shared__ __align__(16) float Bs[2][16*68];
    const int tid = threadIdx.x;
    const int tn = tid & 15;
    const int tm = tid >> 4;
    const int row0 = blockIdx.y*64;
    const int col0 = blockIdx.x*64;
    const int arow = tid >> 2;
    const int acol = (tid & 3) << 2;
    const int brow = tid >> 4;
    const int bcol = (tid & 15) << 2;
    const float* Ap = kv + (size_t)(row0+arow)*128 + acol;
    const float* Bp = B + (size_t)brow*128 + col0 + bcol;
    unsigned long long acc[4][2];
    #pragma unroll
    for (int i = 0; i < 4; i++){ acc[i][0] = 0ull; acc[i][1] = 0ull; }
    float4 av = *(const float4*)Ap;
    float4 bv = *(const float4*)Bp;
    {
        float* Ad = AsD[0];
        *(float2*)&Ad[(acol+0)*136 + 2*arow] = make_float2(av.x, av.x);
        *(float2*)&Ad[(acol+1)*136 + 2*arow] = make_float2(av.y, av.y);
        *(float2*)&Ad[(acol+2)*136 + 2*arow] = make_float2(av.z, av.z);
        *(float2*)&Ad[(acol+3)*136 + 2*arow] = make_float2(av.w, av.w);
        *(float4*)&Bs[0][brow*68 + bcol] = bv;
    }
    __syncthreads();
    #pragma unroll 1
    for (int t = 0; t < 8; t++){
        int cur = t & 1;
        if (t < 7){
            av = *(const float4*)(Ap + (t+1)*16);
            bv = *(const float4*)(Bp + (size_t)(t+1)*16*128);
        }
        const float* Ad = AsD[cur];
        const float* Bb = Bs[cur];
        #pragma unroll
        for (int k = 0; k < 16; k++){
            ulonglong2 aD0 = *reinterpret_cast<const ulonglong2*>(&Ad[k*136 + tm*8]);
            ulonglong2 aD1 = *reinterpret_cast<const ulonglong2*>(&Ad[k*136 + tm*8 + 4]);
            ulonglong2 bp  = *reinterpret_cast<const ulonglong2*>(&Bb[k*68 + tn*4]);
            FMA2(acc[0][0], aD0.x, bp.x); FMA2(acc[0][1], aD0.x, bp.y);
            FMA2(acc[1][0], aD0.y, bp.x); FMA2(acc[1][1], aD0.y, bp.y);
            FMA2(acc[2][0], aD1.x, bp.x); FMA2(acc[2][1], aD1.x, bp.y);
            FMA2(acc[3][0], aD1.y, bp.x); FMA2(acc[3][1], aD1.y, bp.y);
        }
        if (t < 7){
            float* Ad2 = AsD[cur^1];
            *(float2*)&Ad2[(acol+0)*136 + 2*arow] = make_float2(av.x, av.x);
            *(float2*)&Ad2[(acol+1)*136 + 2*arow] = make_float2(av.y, av.y);
            *(float2*)&Ad2[(acol+2)*136 + 2*arow] = make_float2(av.z, av.z);
            *(float2*)&Ad2[(acol+3)*136 + 2*arow] = make_float2(av.w, av.w);
            *(float4*)&Bs[cur^1][brow*68 + bcol] = bv;
        }
        __syncthreads();
    }
    float* h3h = h3 + (size_t)head*NN*384;
    #pragma unroll
    for (int i = 0; i < 4; i++){
        int r = row0 + (tm<<2) + i;
        float* hr = h3h + (size_t)r*384;
        #pragma unroll
        for (int jp = 0; jp < 2; jp++){
            UF2 cv; cv.u = acc[i][jp];
            int col = col0 + (tn<<2) + jp*2;
            float2 q = head ? *(const float2*)(tx + (size_t)(r>>6)*128 + col)
                            : *(const float2*)(q0 + (size_t)r*128 + col);
            *(float2*)(hr + col)       = cv.f;
            *(float2*)(hr + 128 + col) = q;
            *(float2*)(hr + 256 + col) = make_float2(cv.f.x*q.x, cv.f.y*q.y);
        }
    }
}

// ---------------- attention tail: logit + segment softmax ----------------
__global__ void mlp_tail(const float* __restrict__ t2b, const float* __restrict__ W3,
                         float* __restrict__ out0, float* __restrict__ out1){
    __shared__ float sv[64], se[64];
    int b = blockIdx.x, head = blockIdx.y;
    int tid = threadIdx.x;
    int wid = tid >> 5, lane = tid & 31;
    const float* A = t2b + (size_t)head*NN*128;
    const float* w = W3 + (size_t)head*128;
    float w0 = w[lane], w1 = w[lane+32], w2 = w[lane+64], w3v = w[lane+96];
    #pragma unroll
    for (int rr = 0; rr < 8; rr++){
        int node = wid*8 + rr;
        const float* ar = A + (size_t)(b*64 + node)*128;
        float s = ar[lane]*w0 + ar[lane+32]*w1 + ar[lane+64]*w2 + ar[lane+96]*w3v;
        #pragma unroll
        for (int o = 16; o; o >>= 1) s += __shfl_xor_sync(0xffffffffu, s, o);
        if (lane == 0) sv[node] = lrelu(s);
    }
    __syncthreads();
    float e = 0.f, v = 0.f;
    if (tid < 64){
        v = sv[tid];
        float m = -1e30f;
        #pragma unroll 8
        for (int j = 0; j < 64; j++) m = fmaxf(m, sv[j]);
        e = expf(v - m);
        se[tid] = e;
    }
    __syncthreads();
    if (tid < 64){
        float s = 0.f;
        #pragma unroll 8
        for (int j = 0; j < 64; j++) s += se[j];
        float* out = head ? out1 : out0;
        out[b*64 + tid] = e / s;
    }
}

// ---------------- dense edge softmax (with multiplicity) + agg = S^T X ----------------
__global__ __launch_bounds__(256) void esm_agg(const float* __restrict__ CNT,
                                               const float* __restrict__ f1,
                                               const float* __restrict__ f2,
                                               const float* __restrict__ x,
                                               float* __restrict__ STg,
                                               float* __restrict__ agg){
    extern __shared__ float sm[];
    float* sCT = sm;             // 4160
    float* sST = sm + 4160;      // 4160
    float* sX  = sm + 8320;      // 8448
    float* sF1 = sm + 16768;     // 64
    float* sF2 = sm + 16832;     // 64
    int b = blockIdx.x, tid = threadIdx.x;
    for (int i = tid; i < 4096; i += 256)
        sCT[(i>>6)*65 + (i&63)] = CNT[(size_t)b*4096 + i];
    for (int i = tid; i < 8192; i += 256){
        int r = i >> 7, h = i & 127;
        sX[r*132 + h] = x[(size_t)(b*64+r)*128 + h];
    }
    if (tid < 64) sF1[tid] = f1[b*64 + tid];
    else if (tid < 128) sF2[tid-64] = f2[b*64 + tid - 64];
    __syncthreads();
    if (tid < 64){
        int c = tid; float f1c = sF1[c];
        float m = -1e30f;
        for (int r = 0; r < 64; r++)
            if (sCT[c*65+r] > 0.5f)
                m = fmaxf(m, lrelu(f1c + sF2[r]));
        float den = 0.f;
        for (int r = 0; r < 64; r++){
            float cv = sCT[c*65+r];
            float ev = 0.f;
            if (cv > 0.5f){
                ev = cv * expf(lrelu(f1c + sF2[r]) - m);
                den += ev;
            }
            sST[c*65+r] = ev;
        }
        float inv = 1.f / den;
        for (int r = 0; r < 64; r++) sST[c*65+r] *= inv;
    }
    __syncthreads();
    for (int i = tid; i < 4096; i += 256)
        STg[(size_t)b*4096 + i] = sST[(i>>6)*65 + (i&63)];
    const int tc = tid >> 5;
    const int th = (tid & 31) << 2;
    unsigned long long acc[8][2];
    #pragma unroll
    for (int cc = 0; cc < 8; cc++){ acc[cc][0]=0ull; acc[cc][1]=0ull; }
    for (int r = 0; r < 64; r++){
        ulonglong2 xv = *(const ulonglong2*)&sX[r*132 + th];
        #pragma unroll
        for (int cc = 0; cc < 8; cc++){
            UF2 ap; float a = sST[(tc*8+cc)*65 + r];
            ap.f = make_float2(a, a);
            FMA2(acc[cc][0], ap.u, xv.x);
            FMA2(acc[cc][1], ap.u, xv.y);
        }
    }
    #pragma unroll
    for (int cc = 0; cc < 8; cc++){
        ulonglong2 o; o.x = acc[cc][0]; o.y = acc[cc][1];
        *(ulonglong2*)&agg[(size_t)(b*64 + tc*8+cc)*128 + th] = o;
    }
}
__global__ void xc_combine(const float* __restrict__ x, const float* __restrict__ g0,
                           const float* __restrict__ g1, float* __restrict__ xc){
    int idx = blockIdx.x*blockDim.x + threadIdx.x;
    if (idx >= NN*HH) return;
    float xv = x[idx];
    xc[idx] = 0.5f * (lrelu(xv + g0[idx]) + lrelu(xv + g1[idx]));
}

// ---------------- finalize: score softmax + stable top-k + pooled outputs ----------------
__global__ void finalize(const float* __restrict__ g1s, const float* __restrict__ g2s,
                         const float* __restrict__ x,
                         int* __restrict__ perm, float* __restrict__ out){
    __shared__ float sv[64], se[64], ssc[64];
    __shared__ int sperm[KKC];
    int b = blockIdx.x, tid = threadIdx.x;
    float v = 0.f, e = 0.f;
    if (tid < 64){
        int i = b*64 + tid;
        v = g1s[i] + g2s[i];
        sv[tid] = v;
    }
    __syncthreads();
    if (tid < 64){
        float m = -1e30f;
        #pragma unroll 8
        for (int j = 0; j < 64; j++) m = fmaxf(m, sv[j]);
        e = expf(v - m);
        se[tid] = e;
    }
    __syncthreads();
    if (tid < 64){
        float s = 0.f;
        #pragma unroll 8
        for (int j = 0; j < 64; j++) s += se[j];
        float sc = e / s;
        ssc[tid] = sc;
        int rank = 0;
        for (int j = 0; j < 64; j++){
            float vj = sv[j];
            if (vj > v || (vj == v && j < tid)) rank++;
        }
        if (rank < KKC){
            int p = b*KKC + rank;
            sperm[rank] = tid;
            perm[p] = b*64 + tid;
            out[OFF_BATCH + p] = (float)b;
            out[OFF_PERM  + p] = (float)(b*64 + tid);
        }
    }
    __syncthreads();
    for (int idx = tid; idx < KKC*128; idx += blockDim.x){
        int p = idx >> 7, c = idx & 127;
        int node = sperm[p];
        out[OFF_XOUT + ((size_t)b*KKC + p)*128 + c] =
            x[(size_t)(b*64 + node)*128 + c] * ssc[node];
    }
}

// ---------------- dense triple product: U = S_p^T (A S_p) per graph ----------------
__global__ __launch_bounds__(256) void a2_dense(const float* __restrict__ AT,
                                                const float* __restrict__ STg,
                                                const int* __restrict__ perm,
                                                float* __restrict__ U){
    __shared__ float sA[4160], sS[4160], sT[64*53];
    __shared__ int sp[KKC];
    int b = blockIdx.x, tid = threadIdx.x;
    for (int i = tid; i < 4096; i += 256){
        int o = (i>>6)*65 + (i&63);
        sA[o] = AT[(size_t)b*4096 + i];
        sS[o] = STg[(size_t)b*4096 + i];
    }
    if (tid < KKC) sp[tid] = perm[b*KKC + tid] & 63;
    __syncthreads();
    {
        int r = tid & 63;
        for (int j = tid >> 6; j < KKC; j += 4){
            int pj = sp[j];
            float acc = 0.f;
            for (int k = 0; k < 64; k++)
                acc = fmaf(sA[k*65 + r], sS[pj*65 + k], acc);
            sT[r*53 + j] = acc;
        }
    }
    __syncthreads();
    {
        int i = tid & 63;
        if (i < KKC){
            int pi = sp[i];
            for (int j = tid >> 6; j < KKC; j += 4){
                float acc = 0.f;
                for (int r = 0; r < 64; r++)
                    acc = fmaf(sS[pi*65 + r], sT[r*53 + j], acc);
                U[(size_t)b*(KKC*KKC) + i*KKC + j] = acc;
            }
        }
    }
}
// write full A2 rows (zero fill + band + unit diag)
__global__ void a2_write(const float* __restrict__ U, float* __restrict__ outA2){
    __shared__ float sU[KKC];
    int p = blockIdx.x, tid = threadIdx.x;
    int b = p / KKC;
    int li = p - b*KKC;
    if (tid < KKC) sU[tid] = U[(size_t)b*(KKC*KKC) + li*KKC + tid];
    __syncthreads();
    int base = b*KKC;
    float* row = outA2 + (size_t)p*NKC;
    for (int t = tid; t < NKC; t += 256){
        unsigned kk = (unsigned)(t - base);
        float v = (kk < (unsigned)KKC) ? sU[kk] : 0.f;
        if (t == p) v = 1.0f;
        row[t] = v;
    }
}

// ---------------- host launcher ----------------
extern "C" void kernel_launch(void* const* d_in, const int* in_sizes, int n_in,
                              void* d_out, int out_size){
    const float* x    = (const float*)d_in[0];
    const int*   ei   = (const int*)  d_in[1];
    const float* ewt  = (const float*)d_in[2];
    const float* tx   = (const float*)d_in[3];
    const float* Wk   = (const float*)d_in[5];
    const float* W1   = (const float*)d_in[6];
    const float* W2   = (const float*)d_in[7];
    const float* W3   = (const float*)d_in[8];
    const float* linW = (const float*)d_in[9];
    float* out = (float*)d_out;

    void* basep = nullptr;
    cudaGetSymbolAddress(&basep, d_scratch);
    float* base = (float*)basep;

    float* deg   = base + O_DEG;
    float* AT    = base + O_AT;
    float* CNT   = base + O_CNTT;
    float* dinv  = base + O_DINV;
    float* STg   = base + O_ST;
    float* U     = base + O_U;
    float* h3    = base + O_H3;
    float* t1    = base + O_T1;
    float* t2    = base + O_T2;
    float* xq    = base + O_XQ;
    float* agg   = base + O_AGG;
    float* g0    = base + O_G0;
    float* g1b   = g0 + (size_t)NN*128;
    float* xc    = base + O_XC;
    float* xq2   = base + O_XQ2;
    float* f1    = base + O_F1;
    float* f2    = base + O_F2;
    float* g1s   = base + O_G1S;
    float* g2s   = base + O_G2S;
    int*   perm  = (int*)(base + O_PERM);
    float* W1e   = base + O_W1E;

    static bool attr_done = false;
    if (!attr_done){
        cudaFuncSetAttribute(hop2_dense, cudaFuncAttributeMaxDynamicSharedMemorySize, 84224);
        cudaFuncSetAttribute(esm_agg,    cudaFuncAttributeMaxDynamicSharedMemorySize, 67584);
        attr_done = true;
    }

    const int EG = (NEC + 255)/256;
    const size_t S128 = (size_t)NN*128;

    // ---- graph prep ----
    prep0<<<32 + (4*384*256+255)/256, 256>>>((float4*)base, W1, W1e);
    edge_pass1<<<EG,256>>>(ei, ewt, deg);
    compute_dinv<<<16,256>>>(deg, dinv);
    dense_build<<<EG,256>>>(ei, ewt, dinv, AT, CNT);

    // ---- x_q = hop(hop(x)) ----
    hop2_dense<<<BB,256,84224>>>(x, xq, AT);

    // ---- attention pair (2 heads batched over blockIdx.z) ----
    auto attention_pair = [&](const float* kv, const float* q0, int pairbase,
                              float* out0, float* out1){
        gemm_h3<<<dim3(2,64,2),256>>>(kv, Wk + (size_t)pairbase*128*128, q0, tx, h3);
        gemm64p<<<dim3(4,64,2),256>>>(h3, W1e + (size_t)pairbase*384*256, t1,
                                      256, 384, 1, (size_t)NN*384, (size_t)384*256, (size_t)NN*256);
        gemm64p<<<dim3(2,64,2),256>>>(t1, W2 + (size_t)pairbase*256*128, t2,
                                      128, 256, 1, (size_t)NN*256, (size_t)256*128, S128);
        mlp_tail<<<dim3(BB,2),256>>>(t2, W3 + (size_t)pairbase*128, out0, out1);
    };

    attention_pair(x, xq, 0, f1, f2);

    // ---- dense edge softmax + aggregation ----
    esm_agg<<<BB,256,67584>>>(CNT, f1, f2, x, STg, agg);
    gemm64p<<<dim3(2,64,2),256>>>(agg, linW, g0, 128, 128, 0,
                                  0, (size_t)128*128, S128);
    xc_combine<<<2048,256>>>(x, g0, g1b, xc);

    // ---- second round ----
    hop2_dense<<<BB,256,84224>>>(xc, xq2, AT);
    attention_pair(xc, xq2, 2, g1s, g2s);

    // ---- score softmax + top-k + pooled outputs ----
    finalize<<<BB,256>>>(g1s, g2s, x, perm, out);

    // ---- A2 = S_p^T (A_d S_p) dense per graph ----
    a2_dense<<<BB,256>>>(AT, STg, perm, U);
    a2_write<<<NKC,256>>>(U, out + OFF_A2);
}